// round 1
// baseline (speedup 1.0000x reference)
#include <cuda_runtime.h>
#include <math.h>

// Problem constants (fixed shapes)
constexpr int Bb   = 4;
constexpr int Tt   = 4096;
constexpr int Ddim = 1024;           // K
constexpr int Hdim = 1024;           // N per weight matrix
constexpr int Mtot = Bb * Tt;        // 16384 rows
constexpr long long PLANE = (long long)Mtot * Hdim;   // 16,777,216

// Chunked scan config
constexpr int NC = 128;              // chunks along T
constexpr int LC = Tt / NC;          // 32 steps per chunk

// Scratch (device globals; allocation-free per harness rules)
// g_z holds 3 planes: zf, zi, zh. After gates_kernel: plane0 = f, plane1 = v.
__device__ float g_z[3 * PLANE];
__device__ float g_F [Bb * NC * Hdim];
__device__ float g_V [Bb * NC * Hdim];
__device__ float g_Hs[Bb * NC * Hdim];

// ---------------------------------------------------------------------------
// f32x2 packed helpers (Blackwell FFMA2 path — only reachable via PTX)
// ---------------------------------------------------------------------------
__device__ __forceinline__ unsigned long long pack2(float lo, float hi) {
    unsigned long long r;
    asm("mov.b64 %0, {%1, %2};" : "=l"(r) : "f"(lo), "f"(hi));
    return r;
}
__device__ __forceinline__ void unpack2(unsigned long long v, float& lo, float& hi) {
    asm("mov.b64 {%0, %1}, %2;" : "=f"(lo), "=f"(hi) : "l"(v));
}
__device__ __forceinline__ unsigned long long fma2(unsigned long long a,
                                                   unsigned long long b,
                                                   unsigned long long c) {
    unsigned long long d;
    asm("fma.rn.f32x2 %0, %1, %2, %3;" : "=l"(d) : "l"(a), "l"(b), "l"(c));
    return d;
}

// Stable scalar math
__device__ __forceinline__ float softplusf(float x) {
    // log(1+exp(x)) = max(x,0) + log1p(exp(-|x|))
    return fmaxf(x, 0.0f) + log1pf(expf(-fabsf(x)));
}
__device__ __forceinline__ float sigmf(float x) {
    float e = expf(-fabsf(x));
    return (x >= 0.0f) ? 1.0f / (1.0f + e) : e / (1.0f + e);
}

// ---------------------------------------------------------------------------
// GEMM: Z[mat] = X(16384x1024) * W[mat]^T(1024x1024) + bias[mat]
// Both X rows and W rows are K-contiguous (NT GEMM).
// BM=BN=128, BK=8, 256 threads, 8x8 per thread, fp32x2 packed FMA.
// Grid: x = 24 n-tiles (3 mats x 8 tiles of 128), y = 128 m-tiles.
// ---------------------------------------------------------------------------
#define BM 128
#define BN 128
#define BK 8

__global__ __launch_bounds__(256, 2)
void gemm_kernel(const float* __restrict__ X,
                 const float* __restrict__ Wf, const float* __restrict__ Wi,
                 const float* __restrict__ Wh,
                 const float* __restrict__ bf, const float* __restrict__ bi,
                 const float* __restrict__ bh)
{
    __shared__ float As[2][BK][132];   // [k][m], padded stride 132
    __shared__ float Bs[2][BK][132];   // [k][n]

    const int nblk = blockIdx.x;          // 0..23
    const int mblk = blockIdx.y;          // 0..127
    const int mat  = nblk >> 3;           // 0,1,2
    const int nloc = (nblk & 7) * BN;     // column within the H=1024 plane

    const float* W    = (mat == 0) ? Wf : (mat == 1) ? Wi : Wh;
    const float* bias = (mat == 0) ? bf : (mat == 1) ? bi : bh;
    float* Z = g_z + (long long)mat * PLANE;

    const int tid  = threadIdx.x;
    const int lrow = tid >> 1;            // 0..127
    const int lcol = (tid & 1) * 4;       // 0 or 4

    const float* Aptr = X + (long long)(mblk * BM + lrow) * Ddim + lcol;
    const float* Bptr = W + (long long)(nloc + lrow) * Ddim + lcol;

    const int tm = (tid & 15) * 8;        // m offset within tile
    const int tn = (tid >> 4) * 8;        // n offset within tile

    unsigned long long acc[4][8];
    #pragma unroll
    for (int i = 0; i < 4; i++)
        #pragma unroll
        for (int j = 0; j < 8; j++) acc[i][j] = 0ull;

    // Prefetch tile 0 into smem buffer 0
    float4 aReg = *(const float4*)(Aptr);
    float4 bReg = *(const float4*)(Bptr);
    As[0][lcol + 0][lrow] = aReg.x; As[0][lcol + 1][lrow] = aReg.y;
    As[0][lcol + 2][lrow] = aReg.z; As[0][lcol + 3][lrow] = aReg.w;
    Bs[0][lcol + 0][lrow] = bReg.x; Bs[0][lcol + 1][lrow] = bReg.y;
    Bs[0][lcol + 2][lrow] = bReg.z; Bs[0][lcol + 3][lrow] = bReg.w;
    __syncthreads();

    const int nk = Ddim / BK;             // 128 k-tiles
    for (int kt = 0; kt < nk; kt++) {
        const int buf = kt & 1;
        if (kt + 1 < nk) {
            aReg = *(const float4*)(Aptr + (kt + 1) * BK);
            bReg = *(const float4*)(Bptr + (kt + 1) * BK);
        }
        #pragma unroll
        for (int k = 0; k < BK; k++) {
            float4 a0 = *(const float4*)&As[buf][k][tm];
            float4 a1 = *(const float4*)&As[buf][k][tm + 4];
            float4 b0 = *(const float4*)&Bs[buf][k][tn];
            float4 b1 = *(const float4*)&Bs[buf][k][tn + 4];
            unsigned long long a2[4] = { pack2(a0.x, a0.y), pack2(a0.z, a0.w),
                                         pack2(a1.x, a1.y), pack2(a1.z, a1.w) };
            float bv[8] = { b0.x, b0.y, b0.z, b0.w, b1.x, b1.y, b1.z, b1.w };
            #pragma unroll
            for (int j = 0; j < 8; j++) {
                unsigned long long bb = pack2(bv[j], bv[j]);
                #pragma unroll
                for (int i = 0; i < 4; i++)
                    acc[i][j] = fma2(a2[i], bb, acc[i][j]);
            }
        }
        if (kt + 1 < nk) {
            const int nbuf = buf ^ 1;
            As[nbuf][lcol + 0][lrow] = aReg.x; As[nbuf][lcol + 1][lrow] = aReg.y;
            As[nbuf][lcol + 2][lrow] = aReg.z; As[nbuf][lcol + 3][lrow] = aReg.w;
            Bs[nbuf][lcol + 0][lrow] = bReg.x; Bs[nbuf][lcol + 1][lrow] = bReg.y;
            Bs[nbuf][lcol + 2][lrow] = bReg.z; Bs[nbuf][lcol + 3][lrow] = bReg.w;
            __syncthreads();
        }
    }

    // Epilogue: unpack, add bias, store 8x8 tile
    float c[8][8];
    #pragma unroll
    for (int i = 0; i < 4; i++)
        #pragma unroll
        for (int j = 0; j < 8; j++)
            unpack2(acc[i][j], c[2 * i][j], c[2 * i + 1][j]);

    const int gm = mblk * BM + tm;
    const int gn = nloc + tn;
    float4 bv0 = *(const float4*)&bias[gn];
    float4 bv1 = *(const float4*)&bias[gn + 4];
    #pragma unroll
    for (int r = 0; r < 8; r++) {
        float4 o0 = make_float4(c[r][0] + bv0.x, c[r][1] + bv0.y,
                                c[r][2] + bv0.z, c[r][3] + bv0.w);
        float4 o1 = make_float4(c[r][4] + bv1.x, c[r][5] + bv1.y,
                                c[r][6] + bv1.z, c[r][7] + bv1.w);
        float* zr = Z + (long long)(gm + r) * Hdim + gn;
        *(float4*)(zr)     = o0;
        *(float4*)(zr + 4) = o1;
    }
}

// ---------------------------------------------------------------------------
// Gates: in-place on z planes. plane0 <- f = sigmoid(-diff); plane1 <- v = i*g
// ---------------------------------------------------------------------------
__global__ __launch_bounds__(256)
void gates_kernel()
{
    long long i4 = (long long)blockIdx.x * blockDim.x + threadIdx.x;   // float4 index
    const float4 zf4 = ((const float4*)(g_z            ))[i4];
    const float4 zi4 = ((const float4*)(g_z +     PLANE))[i4];
    const float4 zh4 = ((const float4*)(g_z + 2 * PLANE))[i4];

    float f[4], v[4];
    const float zf[4] = { zf4.x, zf4.y, zf4.z, zf4.w };
    const float zi[4] = { zi4.x, zi4.y, zi4.z, zi4.w };
    const float zh[4] = { zh4.x, zh4.y, zh4.z, zh4.w };
    #pragma unroll
    for (int l = 0; l < 4; l++) {
        float diff = softplusf(-zf[l]) - softplusf(-zi[l]);
        float ff = sigmf(-diff);
        float ii = sigmf(diff);
        float gg = (zh[l] >= 0.0f) ? (zh[l] + 0.5f) : sigmf(zh[l]);
        f[l] = ff;
        v[l] = ii * gg;
    }
    ((float4*)(g_z        ))[i4] = make_float4(f[0], f[1], f[2], f[3]);
    ((float4*)(g_z + PLANE))[i4] = make_float4(v[0], v[1], v[2], v[3]);
}

// ---------------------------------------------------------------------------
// Scan pass 1: per-(b, chunk, h) aggregates  F = prod f,  V = local scan end
// ---------------------------------------------------------------------------
__global__ __launch_bounds__(1024)
void chunk_scan_kernel()
{
    const int h = threadIdx.x;            // 0..1023
    const int c = blockIdx.x;             // chunk
    const int b = blockIdx.y;             // batch
    const float* fp = g_z + ((long long)(b * Tt + c * LC)) * Hdim + h;
    const float* vp = fp + PLANE;
    float F = 1.0f, V = 0.0f;
    #pragma unroll 8
    for (int l = 0; l < LC; l++) {
        float f = fp[(long long)l * Hdim];
        float v = vp[(long long)l * Hdim];
        V = fmaf(f, V, v);
        F *= f;
    }
    const int o = (b * NC + c) * Hdim + h;
    g_F[o] = F;
    g_V[o] = V;
}

// ---------------------------------------------------------------------------
// Scan pass 2: sequential over chunks, record h at each chunk start
// ---------------------------------------------------------------------------
__global__ __launch_bounds__(256)
void chunk_prefix_kernel(const float* __restrict__ h0)
{
    const int gid = blockIdx.x * blockDim.x + threadIdx.x;  // 0..4095 over (b,h)
    const int b  = gid >> 10;
    const int hh = gid & 1023;
    const float x = h0[gid];
    float run = (x >= 0.0f) ? (x + 0.5f) : sigmf(x);        // g(h_0)
    for (int c = 0; c < NC; c++) {
        const int o = (b * NC + c) * Hdim + hh;
        g_Hs[o] = run;
        run = fmaf(g_F[o], run, g_V[o]);
    }
}

// ---------------------------------------------------------------------------
// Scan pass 3: apply within-chunk scan with correct initial h, write output
// ---------------------------------------------------------------------------
__global__ __launch_bounds__(1024)
void apply_kernel(float* __restrict__ out)
{
    const int h = threadIdx.x;
    const int c = blockIdx.x;
    const int b = blockIdx.y;
    float run = g_Hs[(b * NC + c) * Hdim + h];
    const float* fp = g_z + ((long long)(b * Tt + c * LC)) * Hdim + h;
    const float* vp = fp + PLANE;
    float* op = out + ((long long)(b * Tt + c * LC)) * Hdim + h;
    #pragma unroll 8
    for (int l = 0; l < LC; l++) {
        float f = fp[(long long)l * Hdim];
        float v = vp[(long long)l * Hdim];
        run = fmaf(f, run, v);
        op[(long long)l * Hdim] = run;
    }
}

// ---------------------------------------------------------------------------
extern "C" void kernel_launch(void* const* d_in, const int* in_sizes, int n_in,
                              void* d_out, int out_size)
{
    (void)in_sizes; (void)n_in; (void)out_size;
    const float* x  = (const float*)d_in[0];
    const float* h0 = (const float*)d_in[1];
    const float* Wf = (const float*)d_in[2];
    const float* bf = (const float*)d_in[3];
    const float* Wi = (const float*)d_in[4];
    const float* bi = (const float*)d_in[5];
    const float* Wh = (const float*)d_in[6];
    const float* bh = (const float*)d_in[7];
    float* out = (float*)d_out;

    dim3 gGemm(24, 128);                                   // 3 mats x 8 n-tiles, 128 m-tiles
    gemm_kernel<<<gGemm, 256>>>(x, Wf, Wi, Wh, bf, bi, bh);

    const long long nvec = PLANE / 4;                      // float4 elements
    gates_kernel<<<(unsigned)(nvec / 256), 256>>>();

    chunk_scan_kernel<<<dim3(NC, Bb), 1024>>>();
    chunk_prefix_kernel<<<16, 256>>>(h0);
    apply_kernel<<<dim3(NC, Bb), 1024>>>(out);
}

// round 3
// speedup vs baseline: 3.4343x; 3.4343x over previous
#include <cuda_runtime.h>
#include <cuda.h>
#include <cstdint>
#include <math.h>

// ---------------- problem constants ----------------
constexpr int Bb = 4, Tt = 4096, Hdim = 1024, Ddim = 1024;
constexpr int Mtot = Bb * Tt;                         // 16384
constexpr long long PLANE = (long long)Mtot * Hdim;   // 16,777,216
constexpr int NC = 128, LCc = 32;

// Scratch (device globals; allocation-free)
__device__ float g_z[2 * PLANE];                      // plane0 = f, plane1 = v
__device__ float g_xr[PLANE];                         // tf32-rounded x
__device__ float g_wr[3 * Ddim * Hdim];               // tf32-rounded Wf|Wi|Wh
__device__ float g_F [Bb * NC * Hdim];
__device__ float g_V [Bb * NC * Hdim];
__device__ float g_Hs[Bb * NC * Hdim];

// ---------------- PTX helpers (base sm_103 target only!) ----------------
__device__ __forceinline__ uint32_t smem_u32(const void* p) {
    uint32_t a;
    asm("{ .reg .u64 t; cvta.to.shared.u64 t, %1; cvt.u32.u64 %0, t; }" : "=r"(a) : "l"(p));
    return a;
}
__device__ __forceinline__ void mbar_init(uint32_t a, uint32_t cnt) {
    asm volatile("mbarrier.init.shared.b64 [%0], %1;" :: "r"(a), "r"(cnt) : "memory");
}
__device__ __forceinline__ void mbar_expect_tx(uint32_t a, uint32_t bytes) {
    asm volatile("mbarrier.arrive.expect_tx.shared.b64 _, [%0], %1;" :: "r"(a), "r"(bytes) : "memory");
}
__device__ __forceinline__ void mbar_wait(uint32_t a, uint32_t parity) {
    asm volatile(
        "{\n\t.reg .pred P;\n\t"
        "WL%=:\n\t"
        "mbarrier.try_wait.parity.acquire.cta.shared::cta.b64 P, [%0], %1, 0x989680;\n\t"
        "@!P bra WL%=;\n\t}"
        :: "r"(a), "r"(parity) : "memory");
}
__device__ __forceinline__ void tma_2d(uint32_t dst, const CUtensorMap* m, int x, int y, uint32_t mbar) {
    asm volatile(
        "cp.async.bulk.tensor.2d.shared::cta.global.tile.mbarrier::complete_tx::bytes "
        "[%0], [%1, {%2, %3}], [%4];"
        :: "r"(dst), "l"(m), "r"(x), "r"(y), "r"(mbar) : "memory");
}
// tf32 m16n8k8 HMMA (sm_80+, base target)
__device__ __forceinline__ void mma8(float* d, const uint32_t* a, uint32_t b0, uint32_t b1) {
    asm volatile(
        "mma.sync.aligned.m16n8k8.row.col.f32.tf32.tf32.f32 "
        "{%0,%1,%2,%3}, {%4,%5,%6,%7}, {%8,%9}, {%0,%1,%2,%3};"
        : "+f"(d[0]), "+f"(d[1]), "+f"(d[2]), "+f"(d[3])
        : "r"(a[0]), "r"(a[1]), "r"(a[2]), "r"(a[3]), "r"(b0), "r"(b1));
}
__device__ __forceinline__ float tf32r(float x) {
    uint32_t u; asm("cvt.rna.tf32.f32 %0, %1;" : "=r"(u) : "f"(x));
    return __uint_as_float(u);
}
// swizzled LDS of one b32 from a SW128 tile (128B rows)
__device__ __forceinline__ uint32_t ldsw(const char* base, int r, int c) {
    int off = (r << 7) | (c << 2);
    off ^= (off >> 3) & 0x70;
    return *(const uint32_t*)(base + off);
}

// ---------------- scalar math ----------------
__device__ __forceinline__ float softplusf(float x) {
    return fmaxf(x, 0.0f) + log1pf(expf(-fabsf(x)));
}
__device__ __forceinline__ float sigmf(float x) {
    float e = expf(-fabsf(x));
    return (x >= 0.0f) ? 1.0f / (1.0f + e) : e / (1.0f + e);
}

// ---------------- prep: round inputs to tf32 once ----------------
__global__ __launch_bounds__(256)
void round_x_kernel(const float4* __restrict__ in) {
    const int i = blockIdx.x * 256 + threadIdx.x;          // 16M/4 = 4,194,304 threads
    float4 v = in[i];
    v.x = tf32r(v.x); v.y = tf32r(v.y); v.z = tf32r(v.z); v.w = tf32r(v.w);
    ((float4*)g_xr)[i] = v;
}
__global__ __launch_bounds__(256)
void round_w_kernel(const float4* __restrict__ wf, const float4* __restrict__ wi,
                    const float4* __restrict__ wh) {
    const int i = blockIdx.x * 256 + threadIdx.x;          // 262144 threads
    float4 a = wf[i], b = wi[i], c = wh[i];
    a.x = tf32r(a.x); a.y = tf32r(a.y); a.z = tf32r(a.z); a.w = tf32r(a.w);
    b.x = tf32r(b.x); b.y = tf32r(b.y); b.z = tf32r(b.z); b.w = tf32r(b.w);
    c.x = tf32r(c.x); c.y = tf32r(c.y); c.z = tf32r(c.z); c.w = tf32r(c.w);
    ((float4*)g_wr)[i]          = a;
    ((float4*)g_wr)[i + 262144] = b;
    ((float4*)g_wr)[i + 524288] = c;
}

// ---------------- fused GEMM (HMMA tf32) + gates ----------------
// CTA tile: M=128 x N=64, all 3 mats. 8 warps (4m x 2n), warp tile 32x32.
// 4-stage TMA ring: stage = A(128x32, 16KB) + 3x B(64x32, 8KB) = 40KB.
constexpr int STAGES = 4;
constexpr int STAGE_BYTES = 40960;
constexpr int S_DATA = 1024;
constexpr int SMEM_GEMM = S_DATA + STAGES * STAGE_BYTES;   // 164,864

__global__ __launch_bounds__(256, 1)
void gemm_kernel(const __grid_constant__ CUtensorMap tA,
                 const __grid_constant__ CUtensorMap tB0,
                 const __grid_constant__ CUtensorMap tB1,
                 const __grid_constant__ CUtensorMap tB2,
                 const float* __restrict__ bf, const float* __restrict__ bi,
                 const float* __restrict__ bh)
{
    extern __shared__ char smem[];
    const uint32_t sb = smem_u32(smem);
    const int tid  = threadIdx.x;
    const int lane = tid & 31;
    const int wid  = tid >> 5;
    const int wm   = wid & 3;          // 0..3
    const int wn   = wid >> 2;         // 0..1
    const int m0   = blockIdx.x * 128;
    const int n0   = blockIdx.y * 64;
    const int gr   = lane >> 2;        // 0..7
    const int gc   = lane & 3;         // 0..3

    if (tid == 0)
        for (int s = 0; s < STAGES; s++) mbar_init(sb + s * 8, 1);
    __syncthreads();
    if (tid == 0) {
        for (int s = 0; s < STAGES; s++) {
            mbar_expect_tx(sb + s * 8, STAGE_BYTES);
            const uint32_t st = sb + S_DATA + s * STAGE_BYTES;
            tma_2d(st,         &tA,  s * 32, m0, sb + s * 8);
            tma_2d(st + 16384, &tB0, s * 32, n0, sb + s * 8);
            tma_2d(st + 24576, &tB1, s * 32, n0, sb + s * 8);
            tma_2d(st + 32768, &tB2, s * 32, n0, sb + s * 8);
        }
    }

    float acc[3][2][4][4];
    #pragma unroll
    for (int m = 0; m < 3; m++)
        #pragma unroll
        for (int i = 0; i < 2; i++)
            #pragma unroll
            for (int j = 0; j < 4; j++)
                #pragma unroll
                for (int r = 0; r < 4; r++) acc[m][i][j][r] = 0.0f;

    for (int kt = 0; kt < 32; kt++) {
        const int s = kt & 3;
        mbar_wait(sb + s * 8, (kt >> 2) & 1);
        const char* stg = smem + S_DATA + s * STAGE_BYTES;

        #pragma unroll
        for (int k = 0; k < 4; k++) {
            const int c0 = k * 8 + gc;
            uint32_t af[2][4];
            #pragma unroll
            for (int ms = 0; ms < 2; ms++) {
                const int r = wm * 32 + ms * 16 + gr;
                af[ms][0] = ldsw(stg, r,     c0);
                af[ms][1] = ldsw(stg, r + 8, c0);
                af[ms][2] = ldsw(stg, r,     c0 + 4);
                af[ms][3] = ldsw(stg, r + 8, c0 + 4);
            }
            #pragma unroll
            for (int mat = 0; mat < 3; mat++) {
                const char* Bb_ = stg + 16384 + mat * 8192;
                #pragma unroll
                for (int ns = 0; ns < 4; ns++) {
                    const int rB = wn * 32 + ns * 8 + gr;
                    const uint32_t b0 = ldsw(Bb_, rB, c0);
                    const uint32_t b1 = ldsw(Bb_, rB, c0 + 4);
                    mma8(acc[mat][0][ns], af[0], b0, b1);
                    mma8(acc[mat][1][ns], af[1], b0, b1);
                }
            }
        }
        __syncthreads();
        if (tid == 0 && kt + STAGES < 32) {
            mbar_expect_tx(sb + s * 8, STAGE_BYTES);
            const uint32_t st = sb + S_DATA + s * STAGE_BYTES;
            const int kk = (kt + STAGES) * 32;
            tma_2d(st,         &tA,  kk, m0, sb + s * 8);
            tma_2d(st + 16384, &tB0, kk, n0, sb + s * 8);
            tma_2d(st + 24576, &tB1, kk, n0, sb + s * 8);
            tma_2d(st + 32768, &tB2, kk, n0, sb + s * 8);
        }
    }

    // ---- register epilogue: gates, write f,v planes ----
    #pragma unroll
    for (int ms = 0; ms < 2; ms++) {
        #pragma unroll
        for (int ns = 0; ns < 4; ns++) {
            const int col = n0 + wn * 32 + ns * 8 + gc * 2;
            const float2 Bf = *(const float2*)(bf + col);
            const float2 Bi = *(const float2*)(bi + col);
            const float2 Bh = *(const float2*)(bh + col);
            #pragma unroll
            for (int hf = 0; hf < 2; hf++) {
                const int row = m0 + wm * 32 + ms * 16 + gr + hf * 8;
                const float zf0 = acc[0][ms][ns][hf * 2 + 0] + Bf.x;
                const float zf1 = acc[0][ms][ns][hf * 2 + 1] + Bf.y;
                const float zi0 = acc[1][ms][ns][hf * 2 + 0] + Bi.x;
                const float zi1 = acc[1][ms][ns][hf * 2 + 1] + Bi.y;
                const float zh0 = acc[2][ms][ns][hf * 2 + 0] + Bh.x;
                const float zh1 = acc[2][ms][ns][hf * 2 + 1] + Bh.y;
                const float d0 = softplusf(-zf0) - softplusf(-zi0);
                const float d1 = softplusf(-zf1) - softplusf(-zi1);
                const float f0 = sigmf(-d0), f1 = sigmf(-d1);
                const float g0 = (zh0 >= 0.0f) ? (zh0 + 0.5f) : sigmf(zh0);
                const float g1 = (zh1 >= 0.0f) ? (zh1 + 0.5f) : sigmf(zh1);
                const float v0 = sigmf(d0) * g0;
                const float v1 = sigmf(d1) * g1;
                const long long o = (long long)row * Hdim + col;
                *(float2*)(g_z + o)         = make_float2(f0, f1);
                *(float2*)(g_z + PLANE + o) = make_float2(v0, v1);
            }
        }
    }
}

// ---------------- scan pass 1: per-chunk aggregates ----------------
__global__ __launch_bounds__(1024)
void chunk_scan_kernel()
{
    const int h = threadIdx.x;
    const int c = blockIdx.x;
    const int b = blockIdx.y;
    const float* fp = g_z + ((long long)(b * Tt + c * LCc)) * Hdim + h;
    const float* vp = fp + PLANE;
    float F = 1.0f, V = 0.0f;
    #pragma unroll 8
    for (int l = 0; l < LCc; l++) {
        const float f = fp[(long long)l * Hdim];
        const float v = vp[(long long)l * Hdim];
        V = fmaf(f, V, v);
        F *= f;
    }
    const int o = (b * NC + c) * Hdim + h;
    g_F[o] = F;
    g_V[o] = V;
}

// ---------------- scan pass 2: warp-parallel affine prefix ----------------
__global__ __launch_bounds__(1024)
void chunk_prefix_kernel(const float* __restrict__ h0)
{
    const int g = blockIdx.x * 32 + (threadIdx.x >> 5);   // warp = (b,h)
    const int l = threadIdx.x & 31;
    const int b = g >> 10;
    const int h = g & 1023;

    float Fk[4], Vk[4];
    #pragma unroll
    for (int k = 0; k < 4; k++) {
        const int o = (b * NC + 4 * l + k) * Hdim + h;
        Fk[k] = g_F[o];
        Vk[k] = g_V[o];
    }
    float Fa = Fk[0], Va = Vk[0];
    #pragma unroll
    for (int k = 1; k < 4; k++) { Va = fmaf(Fk[k], Va, Vk[k]); Fa *= Fk[k]; }
    #pragma unroll
    for (int d = 1; d < 32; d <<= 1) {
        const float Fo = __shfl_up_sync(0xFFFFFFFF, Fa, d);
        const float Vo = __shfl_up_sync(0xFFFFFFFF, Va, d);
        if (l >= d) { Va = fmaf(Fa, Vo, Va); Fa *= Fo; }
    }
    float Fe = __shfl_up_sync(0xFFFFFFFF, Fa, 1);
    float Ve = __shfl_up_sync(0xFFFFFFFF, Va, 1);
    if (l == 0) { Fe = 1.0f; Ve = 0.0f; }

    const float x = h0[b * Hdim + h];
    const float h0p = (x >= 0.0f) ? (x + 0.5f) : sigmf(x);
    float hs = fmaf(Fe, h0p, Ve);
    #pragma unroll
    for (int k = 0; k < 4; k++) {
        g_Hs[(b * NC + 4 * l + k) * Hdim + h] = hs;
        hs = fmaf(Fk[k], hs, Vk[k]);
    }
}

// ---------------- scan pass 3: apply + write output ----------------
__global__ __launch_bounds__(1024)
void apply_kernel(float* __restrict__ out)
{
    const int h = threadIdx.x;
    const int c = blockIdx.x;
    const int b = blockIdx.y;
    float run = g_Hs[(b * NC + c) * Hdim + h];
    const float* fp = g_z + ((long long)(b * Tt + c * LCc)) * Hdim + h;
    const float* vp = fp + PLANE;
    float* op = out + ((long long)(b * Tt + c * LCc)) * Hdim + h;
    #pragma unroll 8
    for (int l = 0; l < LCc; l++) {
        const float f = fp[(long long)l * Hdim];
        const float v = vp[(long long)l * Hdim];
        run = fmaf(f, run, v);
        op[(long long)l * Hdim] = run;
    }
}

// ---------------- host ----------------
typedef CUresult (*encode_fn_t)(CUtensorMap*, CUtensorMapDataType, cuuint32_t, void*,
                                const cuuint64_t*, const cuuint64_t*, const cuuint32_t*,
                                const cuuint32_t*, CUtensorMapInterleave, CUtensorMapSwizzle,
                                CUtensorMapL2promotion, CUtensorMapFloatOOBfill);

static void make_map(encode_fn_t enc, CUtensorMap* m, const void* ptr,
                     unsigned long long rows, unsigned box_rows)
{
    cuuint64_t dims[2]    = {1024ull, rows};
    cuuint64_t strides[1] = {4096ull};
    cuuint32_t box[2]     = {32u, box_rows};
    cuuint32_t estr[2]    = {1u, 1u};
    enc(m, CU_TENSOR_MAP_DATA_TYPE_FLOAT32, 2, (void*)ptr, dims, strides, box, estr,
        CU_TENSOR_MAP_INTERLEAVE_NONE, CU_TENSOR_MAP_SWIZZLE_128B,
        CU_TENSOR_MAP_L2_PROMOTION_L2_128B, CU_TENSOR_MAP_FLOAT_OOB_FILL_NONE);
}

extern "C" void kernel_launch(void* const* d_in, const int* in_sizes, int n_in,
                              void* d_out, int out_size)
{
    (void)in_sizes; (void)n_in; (void)out_size;
    const float* x  = (const float*)d_in[0];
    const float* h0 = (const float*)d_in[1];
    const float* Wf = (const float*)d_in[2];
    const float* bf = (const float*)d_in[3];
    const float* Wi = (const float*)d_in[4];
    const float* bi = (const float*)d_in[5];
    const float* Wh = (const float*)d_in[6];
    const float* bh = (const float*)d_in[7];
    float* out = (float*)d_out;

    void* xr = nullptr; void* wr = nullptr;
    cudaGetSymbolAddress(&xr, g_xr);
    cudaGetSymbolAddress(&wr, g_wr);

    void* fp = nullptr;
    cudaDriverEntryPointQueryResult qres;
    cudaGetDriverEntryPointByVersion("cuTensorMapEncodeTiled", &fp, 12000,
                                     cudaEnableDefault, &qres);
    encode_fn_t enc = (encode_fn_t)fp;

    CUtensorMap tA, tB0, tB1, tB2;
    make_map(enc, &tA,  xr,                              16384ull, 128u);
    make_map(enc, &tB0, (float*)wr,                      1024ull,  64u);
    make_map(enc, &tB1, (float*)wr + 1024 * 1024,        1024ull,  64u);
    make_map(enc, &tB2, (float*)wr + 2 * 1024 * 1024,    1024ull,  64u);

    cudaFuncSetAttribute(gemm_kernel,
                         cudaFuncAttributeMaxDynamicSharedMemorySize, SMEM_GEMM);

    round_x_kernel<<<16384, 256>>>((const float4*)x);
    round_w_kernel<<<1024, 256>>>((const float4*)Wf, (const float4*)Wi, (const float4*)Wh);
    gemm_kernel<<<dim3(128, 16), 256, SMEM_GEMM>>>(tA, tB0, tB1, tB2, bf, bi, bh);
    chunk_scan_kernel<<<dim3(NC, Bb), 1024>>>();
    chunk_prefix_kernel<<<128, 1024>>>(h0);
    apply_kernel<<<dim3(NC, Bb), 1024>>>(out);
}

// round 5
// speedup vs baseline: 5.2674x; 1.5338x over previous
#include <cuda_runtime.h>
#include <cuda.h>
#include <cuda_fp16.h>
#include <cstdint>
#include <math.h>

// ---------------- problem constants ----------------
constexpr int Bb = 4, Tt = 4096, Hdim = 1024;
constexpr int Mtot = Bb * Tt;                         // 16384
constexpr long long PLANE = (long long)Mtot * Hdim;   // 16,777,216
constexpr int NC = 128, LCc = 32;
constexpr int EPAD = 66;                              // EVEN pad: float2-aligned smem rows

// Scratch (device globals; allocation-free)
__device__ float g_z[2 * PLANE];                      // plane0 = f, plane1 = v
__device__ __align__(1024) __half g_xh[PLANE];        // fp16 x
__device__ __align__(1024) __half g_wh[3u * 1024 * 1024]; // fp16 Wf|Wi|Wh
__device__ float g_F [Bb * NC * Hdim];
__device__ float g_V [Bb * NC * Hdim];
__device__ float g_Hs[Bb * NC * Hdim];

// ---------------- PTX helpers (base sm_103 target only) ----------------
__device__ __forceinline__ uint32_t smem_u32(const void* p) {
    uint32_t a;
    asm("{ .reg .u64 t; cvta.to.shared.u64 t, %1; cvt.u32.u64 %0, t; }" : "=r"(a) : "l"(p));
    return a;
}
__device__ __forceinline__ void mbar_init(uint32_t a, uint32_t cnt) {
    asm volatile("mbarrier.init.shared.b64 [%0], %1;" :: "r"(a), "r"(cnt) : "memory");
}
__device__ __forceinline__ void mbar_expect_tx(uint32_t a, uint32_t bytes) {
    asm volatile("mbarrier.arrive.expect_tx.shared.b64 _, [%0], %1;" :: "r"(a), "r"(bytes) : "memory");
}
__device__ __forceinline__ void mbar_wait(uint32_t a, uint32_t parity) {
    asm volatile(
        "{\n\t.reg .pred P;\n\t"
        "WL%=:\n\t"
        "mbarrier.try_wait.parity.acquire.cta.shared::cta.b64 P, [%0], %1, 0x989680;\n\t"
        "@!P bra WL%=;\n\t}"
        :: "r"(a), "r"(parity) : "memory");
}
__device__ __forceinline__ void tma_2d(uint32_t dst, const CUtensorMap* m, int x, int y, uint32_t mbar) {
    asm volatile(
        "cp.async.bulk.tensor.2d.shared::cta.global.tile.mbarrier::complete_tx::bytes "
        "[%0], [%1, {%2, %3}], [%4];"
        :: "r"(dst), "l"(m), "r"(x), "r"(y), "r"(mbar) : "memory");
}
__device__ __forceinline__ void ldsm4(uint32_t* r, uint32_t addr) {
    asm volatile("ldmatrix.sync.aligned.m8n8.x4.shared.b16 {%0,%1,%2,%3}, [%4];"
                 : "=r"(r[0]), "=r"(r[1]), "=r"(r[2]), "=r"(r[3]) : "r"(addr));
}
__device__ __forceinline__ void mma16(float* d, const uint32_t* a, uint32_t b0, uint32_t b1) {
    asm volatile(
        "mma.sync.aligned.m16n8k16.row.col.f32.f16.f16.f32 "
        "{%0,%1,%2,%3}, {%4,%5,%6,%7}, {%8,%9}, {%0,%1,%2,%3};"
        : "+f"(d[0]), "+f"(d[1]), "+f"(d[2]), "+f"(d[3])
        : "r"(a[0]), "r"(a[1]), "r"(a[2]), "r"(a[3]), "r"(b0), "r"(b1));
}
__device__ __forceinline__ uint32_t f2h2(float a, float b) {
    __half2 h = __floats2half2_rn(a, b);
    return *reinterpret_cast<uint32_t*>(&h);
}

// ---------------- scalar math ----------------
__device__ __forceinline__ float softplusf(float x) {
    return fmaxf(x, 0.0f) + log1pf(expf(-fabsf(x)));
}
__device__ __forceinline__ float sigmf(float x) {
    float e = expf(-fabsf(x));
    return (x >= 0.0f) ? 1.0f / (1.0f + e) : e / (1.0f + e);
}

// ---------------- prep: convert inputs to fp16 ----------------
__global__ __launch_bounds__(256)
void cvt_x_kernel(const float4* __restrict__ in, int base) {
    const int g = base + blockIdx.x * 256 + threadIdx.x;   // 8-float groups
    const float4 v0 = in[2 * g];
    const float4 v1 = in[2 * g + 1];
    uint4 o;
    o.x = f2h2(v0.x, v0.y); o.y = f2h2(v0.z, v0.w);
    o.z = f2h2(v1.x, v1.y); o.w = f2h2(v1.z, v1.w);
    ((uint4*)g_xh)[g] = o;
}
__global__ __launch_bounds__(256)
void cvt_w_kernel(const float4* __restrict__ wf, const float4* __restrict__ wi,
                  const float4* __restrict__ wh) {
    const int g = blockIdx.x * 256 + threadIdx.x;          // 131072 groups per mat
    const float4* src[3] = {wf, wi, wh};
    #pragma unroll
    for (int mat = 0; mat < 3; mat++) {
        const float4 v0 = src[mat][2 * g];
        const float4 v1 = src[mat][2 * g + 1];
        uint4 o;
        o.x = f2h2(v0.x, v0.y); o.y = f2h2(v0.z, v0.w);
        o.z = f2h2(v1.x, v1.y); o.w = f2h2(v1.z, v1.w);
        ((uint4*)g_wh)[mat * 131072 + g] = o;
    }
}

// ---------------- fused GEMM (fp16 HMMA) + gates + chunk aggregates ----------------
// CTA: M=128 x N=64, 3 mats in one pass. 8 warps (4m x 2n), warp tile 32x32x3.
// 4-stage TMA ring, BK=64 halves (128B rows, SW128). Stage = A 16K + 3x B 8K = 40K.
constexpr int STAGES = 4;
constexpr int STAGE_BYTES = 40960;
constexpr int S_DATA = 1024;
constexpr int SMEM_GEMM = S_DATA + STAGES * STAGE_BYTES;   // 164,864
static_assert(S_DATA + 2 * 128 * EPAD * 4 <= SMEM_GEMM, "epilogue fits");

__global__ __launch_bounds__(256, 1)
void gemm_kernel(const __grid_constant__ CUtensorMap tA,
                 const __grid_constant__ CUtensorMap tB0,
                 const __grid_constant__ CUtensorMap tB1,
                 const __grid_constant__ CUtensorMap tB2,
                 const float* __restrict__ bf, const float* __restrict__ bi,
                 const float* __restrict__ bh)
{
    extern __shared__ char smem[];
    const uint32_t sb = smem_u32(smem);
    const int tid  = threadIdx.x;
    const int lane = tid & 31;
    const int wid  = tid >> 5;
    const int wm   = wid & 3;          // 0..3
    const int wn   = wid >> 2;         // 0..1
    const int m0   = blockIdx.x * 128;
    const int n0   = blockIdx.y * 64;
    const int gr   = lane >> 2;        // 0..7 (mma D-frag row)
    const int gc   = lane & 3;         // 0..3

    // ldmatrix lane geometry (SW128: addr = row*128 + (colbyte ^ ((row&7)<<4)))
    const int a_r   = wm * 32 + ((lane >> 3) & 1) * 8 + (lane & 7);
    const int a_kb  = (lane >> 4) * 16;
    const int b_nr  = wn * 32 + ((lane >> 4) & 1) * 8 + (lane & 7);
    const int b_kb  = ((lane >> 3) & 1) * 16;
    const int msk   = (lane & 7) << 4;

    if (tid == 0)
        for (int s = 0; s < STAGES; s++) mbar_init(sb + s * 8, 1);
    __syncthreads();
    if (tid == 0) {
        for (int s = 0; s < STAGES; s++) {
            mbar_expect_tx(sb + s * 8, STAGE_BYTES);
            const uint32_t st = sb + S_DATA + s * STAGE_BYTES;
            tma_2d(st,         &tA,  s * 64, m0, sb + s * 8);
            tma_2d(st + 16384, &tB0, s * 64, n0, sb + s * 8);
            tma_2d(st + 24576, &tB1, s * 64, n0, sb + s * 8);
            tma_2d(st + 32768, &tB2, s * 64, n0, sb + s * 8);
        }
    }

    float acc[3][2][4][4];
    #pragma unroll
    for (int m = 0; m < 3; m++)
        #pragma unroll
        for (int i = 0; i < 2; i++)
            #pragma unroll
            for (int j = 0; j < 4; j++)
                #pragma unroll
                for (int r = 0; r < 4; r++) acc[m][i][j][r] = 0.0f;

    for (int kt = 0; kt < 16; kt++) {
        const int s = kt & 3;
        mbar_wait(sb + s * 8, (kt >> 2) & 1);
        const uint32_t uA = sb + S_DATA + s * STAGE_BYTES;

        #pragma unroll
        for (int ks = 0; ks < 4; ks++) {
            const int axk = (ks * 32 + a_kb) ^ msk;
            const int bxk = (ks * 32 + b_kb) ^ msk;
            uint32_t af[2][4];
            ldsm4(af[0], uA + a_r * 128 + axk);
            ldsm4(af[1], uA + (a_r + 16) * 128 + axk);
            #pragma unroll
            for (int mat = 0; mat < 3; mat++) {
                const uint32_t uB = uA + 16384 + mat * 8192 + b_nr * 128;
                uint32_t bb[2][4];
                ldsm4(bb[0], uB + bxk);
                ldsm4(bb[1], uB + 16 * 128 + bxk);
                #pragma unroll
                for (int ns = 0; ns < 4; ns++) {
                    const uint32_t b0 = bb[ns >> 1][(ns & 1) * 2];
                    const uint32_t b1 = bb[ns >> 1][(ns & 1) * 2 + 1];
                    mma16(acc[mat][0][ns], af[0], b0, b1);
                    mma16(acc[mat][1][ns], af[1], b0, b1);
                }
            }
        }
        __syncthreads();
        if (tid == 0 && kt + STAGES < 16) {
            mbar_expect_tx(sb + s * 8, STAGE_BYTES);
            const uint32_t st = sb + S_DATA + s * STAGE_BYTES;
            const int kk = (kt + STAGES) * 64;
            tma_2d(st,         &tA,  kk, m0, sb + s * 8);
            tma_2d(st + 16384, &tB0, kk, n0, sb + s * 8);
            tma_2d(st + 24576, &tB1, kk, n0, sb + s * 8);
            tma_2d(st + 32768, &tB2, kk, n0, sb + s * 8);
        }
    }

    // ---- epilogue: gates in regs -> smem bounce (reuse stage mem) ----
    float* smf = (float*)(smem + S_DATA);              // 128 x EPAD (even stride!)
    float* smv = smf + 128 * EPAD;
    #pragma unroll
    for (int ms = 0; ms < 2; ms++) {
        #pragma unroll
        for (int ns = 0; ns < 4; ns++) {
            const int col = wn * 32 + ns * 8 + gc * 2;
            const float2 Bf = *(const float2*)(bf + n0 + col);
            const float2 Bi = *(const float2*)(bi + n0 + col);
            const float2 Bh = *(const float2*)(bh + n0 + col);
            #pragma unroll
            for (int hf = 0; hf < 2; hf++) {
                const int row = wm * 32 + ms * 16 + gr + hf * 8;
                const float zf0 = acc[0][ms][ns][hf * 2 + 0] + Bf.x;
                const float zf1 = acc[0][ms][ns][hf * 2 + 1] + Bf.y;
                const float zi0 = acc[1][ms][ns][hf * 2 + 0] + Bi.x;
                const float zi1 = acc[1][ms][ns][hf * 2 + 1] + Bi.y;
                const float zh0 = acc[2][ms][ns][hf * 2 + 0] + Bh.x;
                const float zh1 = acc[2][ms][ns][hf * 2 + 1] + Bh.y;
                const float d0 = softplusf(-zf0) - softplusf(-zi0);
                const float d1 = softplusf(-zf1) - softplusf(-zi1);
                const float f0 = sigmf(-d0), f1 = sigmf(-d1);
                const float g0 = (zh0 >= 0.0f) ? (zh0 + 0.5f) : sigmf(zh0);
                const float g1 = (zh1 >= 0.0f) ? (zh1 + 0.5f) : sigmf(zh1);
                *(float2*)(smf + row * EPAD + col) = make_float2(f0, f1);
                *(float2*)(smv + row * EPAD + col) = make_float2(sigmf(d0) * g0, sigmf(d1) * g1);
            }
        }
    }
    __syncthreads();

    // ---- writeout + fused chunk-scan pass 1 (thread = (chunk, col)) ----
    {
        const int ci  = tid >> 6;          // 0..3
        const int col = tid & 63;
        const int b   = m0 >> 12;
        const int cb  = (m0 & 4095) >> 5;
        float F = 1.0f, V = 0.0f;
        float* gf = g_z + (long long)m0 * Hdim + n0 + col;
        float* gv = gf + PLANE;
        #pragma unroll 8
        for (int r = 0; r < 32; r++) {
            const int row = ci * 32 + r;
            const float f = smf[row * EPAD + col];
            const float v = smv[row * EPAD + col];
            V = fmaf(f, V, v);
            F *= f;
            gf[(long long)row * Hdim] = f;
            gv[(long long)row * Hdim] = v;
        }
        const int o = (b * NC + cb + ci) * Hdim + n0 + col;
        g_F[o] = F;
        g_V[o] = V;
    }
}

// ---------------- chunk prefix: warp-parallel affine scan ----------------
__global__ __launch_bounds__(1024)
void chunk_prefix_kernel(const float* __restrict__ h0)
{
    const int g = blockIdx.x * 32 + (threadIdx.x >> 5);
    const int l = threadIdx.x & 31;
    const int b = g >> 10;
    const int h = g & 1023;

    float Fk[4], Vk[4];
    #pragma unroll
    for (int k = 0; k < 4; k++) {
        const int o = (b * NC + 4 * l + k) * Hdim + h;
        Fk[k] = g_F[o];
        Vk[k] = g_V[o];
    }
    float Fa = Fk[0], Va = Vk[0];
    #pragma unroll
    for (int k = 1; k < 4; k++) { Va = fmaf(Fk[k], Va, Vk[k]); Fa *= Fk[k]; }
    #pragma unroll
    for (int d = 1; d < 32; d <<= 1) {
        const float Fo = __shfl_up_sync(0xFFFFFFFF, Fa, d);
        const float Vo = __shfl_up_sync(0xFFFFFFFF, Va, d);
        if (l >= d) { Va = fmaf(Fa, Vo, Va); Fa *= Fo; }
    }
    float Fe = __shfl_up_sync(0xFFFFFFFF, Fa, 1);
    float Ve = __shfl_up_sync(0xFFFFFFFF, Va, 1);
    if (l == 0) { Fe = 1.0f; Ve = 0.0f; }

    const float x = h0[b * Hdim + h];
    const float h0p = (x >= 0.0f) ? (x + 0.5f) : sigmf(x);
    float hs = fmaf(Fe, h0p, Ve);
    #pragma unroll
    for (int k = 0; k < 4; k++) {
        g_Hs[(b * NC + 4 * l + k) * Hdim + h] = hs;
        hs = fmaf(Fk[k], hs, Vk[k]);
    }
}

// ---------------- apply: within-chunk scan, write output ----------------
__global__ __launch_bounds__(1024)
void apply_kernel(float* __restrict__ out)
{
    const int h = threadIdx.x;
    const int c = blockIdx.x;
    const int b = blockIdx.y;
    float run = g_Hs[(b * NC + c) * Hdim + h];
    const float* fp = g_z + ((long long)(b * Tt + c * LCc)) * Hdim + h;
    const float* vp = fp + PLANE;
    float* op = out + ((long long)(b * Tt + c * LCc)) * Hdim + h;
    #pragma unroll 8
    for (int l = 0; l < LCc; l++) {
        const float f = fp[(long long)l * Hdim];
        const float v = vp[(long long)l * Hdim];
        run = fmaf(f, run, v);
        op[(long long)l * Hdim] = run;
    }
}

// ---------------- host ----------------
typedef CUresult (*encode_fn_t)(CUtensorMap*, CUtensorMapDataType, cuuint32_t, void*,
                                const cuuint64_t*, const cuuint64_t*, const cuuint32_t*,
                                const cuuint32_t*, CUtensorMapInterleave, CUtensorMapSwizzle,
                                CUtensorMapL2promotion, CUtensorMapFloatOOBfill);

static void make_map(encode_fn_t enc, CUtensorMap* m, const void* ptr,
                     unsigned long long rows, unsigned box_rows)
{
    cuuint64_t dims[2]    = {1024ull, rows};
    cuuint64_t strides[1] = {2048ull};                 // fp16 row bytes
    cuuint32_t box[2]     = {64u, box_rows};           // 64 halves = 128B = SW128 atom
    cuuint32_t estr[2]    = {1u, 1u};
    enc(m, CU_TENSOR_MAP_DATA_TYPE_FLOAT16, 2, (void*)ptr, dims, strides, box, estr,
        CU_TENSOR_MAP_INTERLEAVE_NONE, CU_TENSOR_MAP_SWIZZLE_128B,
        CU_TENSOR_MAP_L2_PROMOTION_L2_128B, CU_TENSOR_MAP_FLOAT_OOB_FILL_NONE);
}

extern "C" void kernel_launch(void* const* d_in, const int* in_sizes, int n_in,
                              void* d_out, int out_size)
{
    (void)in_sizes; (void)n_in; (void)out_size;
    const float* x  = (const float*)d_in[0];
    const float* h0 = (const float*)d_in[1];
    const float* Wf = (const float*)d_in[2];
    const float* bf = (const float*)d_in[3];
    const float* Wi = (const float*)d_in[4];
    const float* bi = (const float*)d_in[5];
    const float* Wh = (const float*)d_in[6];
    const float* bh = (const float*)d_in[7];
    float* out = (float*)d_out;

    void* xh = nullptr; void* wh = nullptr;
    cudaGetSymbolAddress(&xh, g_xh);
    cudaGetSymbolAddress(&wh, g_wh);

    void* fp = nullptr;
    cudaDriverEntryPointQueryResult qres;
    cudaGetDriverEntryPointByVersion("cuTensorMapEncodeTiled", &fp, 12000,
                                     cudaEnableDefault, &qres);
    encode_fn_t enc = (encode_fn_t)fp;

    CUtensorMap tA, tB0, tB1, tB2;
    make_map(enc, &tA,  xh,                              16384ull, 128u);
    make_map(enc, &tB0, (__half*)wh,                     1024ull,  64u);
    make_map(enc, &tB1, (__half*)wh + 1024 * 1024,       1024ull,  64u);
    make_map(enc, &tB2, (__half*)wh + 2 * 1024 * 1024,   1024ull,  64u);

    cudaFuncSetAttribute(gemm_kernel,
                         cudaFuncAttributeMaxDynamicSharedMemorySize, SMEM_GEMM);

    // launch order arranged so the GEMM is the 4th launch (ncu -s lands there)
    cvt_x_kernel<<<4096, 256>>>((const float4*)x, 0);
    cvt_x_kernel<<<4096, 256>>>((const float4*)x, 1048576);
    cvt_w_kernel<<<512, 256>>>((const float4*)Wf, (const float4*)Wi, (const float4*)Wh);
    gemm_kernel<<<dim3(128, 16), 256, SMEM_GEMM>>>(tA, tB0, tB1, tB2, bf, bi, bh);
    chunk_prefix_kernel<<<128, 1024>>>(h0);
    apply_kernel<<<dim3(NC, Bb), 1024>>>(out);
}

// round 6
// speedup vs baseline: 6.5635x; 1.2461x over previous
#include <cuda_runtime.h>
#include <cuda.h>
#include <cuda_fp16.h>
#include <cstdint>
#include <math.h>

// ---------------- problem constants ----------------
constexpr int Bb = 4, Tt = 4096, Hdim = 1024;
constexpr int Mtot = Bb * Tt;                         // 16384
constexpr long long PLANE = (long long)Mtot * Hdim;   // 16,777,216
constexpr int NC = 128, LCc = 32;
constexpr int EPAD = 66;                              // even pad: float2-aligned smem rows

// Scratch (device globals; allocation-free)
__device__ float g_z[2 * PLANE];                      // plane0 = f, plane1 = v
__device__ __align__(1024) __half g_xh[PLANE];        // fp16 x
__device__ __align__(1024) __half g_wh[3u * 1024 * 1024]; // fp16 Wf|Wi|Wh
__device__ float g_F [Bb * NC * Hdim];
__device__ float g_V [Bb * NC * Hdim];
__device__ float g_Hs[Bb * NC * Hdim];

// ---------------- PTX helpers (base sm_103 target only) ----------------
__device__ __forceinline__ uint32_t smem_u32(const void* p) {
    uint32_t a;
    asm("{ .reg .u64 t; cvta.to.shared.u64 t, %1; cvt.u32.u64 %0, t; }" : "=r"(a) : "l"(p));
    return a;
}
__device__ __forceinline__ void mbar_init(uint32_t a, uint32_t cnt) {
    asm volatile("mbarrier.init.shared.b64 [%0], %1;" :: "r"(a), "r"(cnt) : "memory");
}
__device__ __forceinline__ void mbar_expect_tx(uint32_t a, uint32_t bytes) {
    asm volatile("mbarrier.arrive.expect_tx.shared.b64 _, [%0], %1;" :: "r"(a), "r"(bytes) : "memory");
}
__device__ __forceinline__ void mbar_wait(uint32_t a, uint32_t parity) {
    asm volatile(
        "{\n\t.reg .pred P;\n\t"
        "WL%=:\n\t"
        "mbarrier.try_wait.parity.acquire.cta.shared::cta.b64 P, [%0], %1, 0x989680;\n\t"
        "@!P bra WL%=;\n\t}"
        :: "r"(a), "r"(parity) : "memory");
}
__device__ __forceinline__ void tma_2d(uint32_t dst, const CUtensorMap* m, int x, int y, uint32_t mbar) {
    asm volatile(
        "cp.async.bulk.tensor.2d.shared::cta.global.tile.mbarrier::complete_tx::bytes "
        "[%0], [%1, {%2, %3}], [%4];"
        :: "r"(dst), "l"(m), "r"(x), "r"(y), "r"(mbar) : "memory");
}
__device__ __forceinline__ void ldsm4(uint32_t* r, uint32_t addr) {
    asm volatile("ldmatrix.sync.aligned.m8n8.x4.shared.b16 {%0,%1,%2,%3}, [%4];"
                 : "=r"(r[0]), "=r"(r[1]), "=r"(r[2]), "=r"(r[3]) : "r"(addr));
}
__device__ __forceinline__ void mma16(float* d, const uint32_t* a, uint32_t b0, uint32_t b1) {
    asm volatile(
        "mma.sync.aligned.m16n8k16.row.col.f32.f16.f16.f32 "
        "{%0,%1,%2,%3}, {%4,%5,%6,%7}, {%8,%9}, {%0,%1,%2,%3};"
        : "+f"(d[0]), "+f"(d[1]), "+f"(d[2]), "+f"(d[3])
        : "r"(a[0]), "r"(a[1]), "r"(a[2]), "r"(a[3]), "r"(b0), "r"(b1));
}
__device__ __forceinline__ uint32_t f2h2(float a, float b) {
    __half2 h = __floats2half2_rn(a, b);
    return *reinterpret_cast<uint32_t*>(&h);
}

// ---------------- scalar math ----------------
__device__ __forceinline__ float softplusf(float x) {
    return fmaxf(x, 0.0f) + log1pf(expf(-fabsf(x)));
}
__device__ __forceinline__ float sigmf(float x) {
    float e = expf(-fabsf(x));
    return (x >= 0.0f) ? 1.0f / (1.0f + e) : e / (1.0f + e);
}

// ---------------- prep: convert inputs to fp16 ----------------
__global__ __launch_bounds__(256)
void cvt_x_kernel(const float4* __restrict__ in, int base) {
    const int g = base + blockIdx.x * 256 + threadIdx.x;   // 8-float groups
    const float4 v0 = in[2 * g];
    const float4 v1 = in[2 * g + 1];
    uint4 o;
    o.x = f2h2(v0.x, v0.y); o.y = f2h2(v0.z, v0.w);
    o.z = f2h2(v1.x, v1.y); o.w = f2h2(v1.z, v1.w);
    ((uint4*)g_xh)[g] = o;
}
__global__ __launch_bounds__(256)
void cvt_w_kernel(const float4* __restrict__ wf, const float4* __restrict__ wi,
                  const float4* __restrict__ wh) {
    const int g = blockIdx.x * 256 + threadIdx.x;          // 131072 groups per mat
    const float4* src[3] = {wf, wi, wh};
    #pragma unroll
    for (int mat = 0; mat < 3; mat++) {
        const float4 v0 = src[mat][2 * g];
        const float4 v1 = src[mat][2 * g + 1];
        uint4 o;
        o.x = f2h2(v0.x, v0.y); o.y = f2h2(v0.z, v0.w);
        o.z = f2h2(v1.x, v1.y); o.w = f2h2(v1.z, v1.w);
        ((uint4*)g_wh)[mat * 131072 + g] = o;
    }
}

// ---------------- fused GEMM (fp16 HMMA) + gates + chunk aggregates ----------------
// CTA: M=128 x N=64, 3 mats in one pass. 8 warps (4m x 2n), warp tile 32x32x3.
// 2-stage TMA ring (smem 82.9 KB -> 2 CTAs/SM, occ 25%).
constexpr int STAGES = 2;
constexpr int STAGE_BYTES = 40960;                   // A 16K + 3x B 8K
constexpr int S_DATA = 1024;
constexpr int SMEM_GEMM = S_DATA + STAGES * STAGE_BYTES;   // 82,944
static_assert(S_DATA + 2 * 128 * EPAD * 4 <= SMEM_GEMM, "epilogue fits");

__global__ __launch_bounds__(256, 2)
void gemm_kernel(const __grid_constant__ CUtensorMap tA,
                 const __grid_constant__ CUtensorMap tB0,
                 const __grid_constant__ CUtensorMap tB1,
                 const __grid_constant__ CUtensorMap tB2,
                 const float* __restrict__ bf, const float* __restrict__ bi,
                 const float* __restrict__ bh)
{
    extern __shared__ char smem[];
    const uint32_t sb = smem_u32(smem);
    const int tid  = threadIdx.x;
    const int lane = tid & 31;
    const int wid  = tid >> 5;
    const int wm   = wid & 3;          // 0..3
    const int wn   = wid >> 2;         // 0..1
    const int m0   = blockIdx.x * 128;
    const int n0   = blockIdx.y * 64;
    const int gr   = lane >> 2;        // 0..7 (mma D-frag row)
    const int gc   = lane & 3;         // 0..3

    // ldmatrix lane geometry (SW128: addr = row*128 + (colbyte ^ ((row&7)<<4)))
    const int a_r   = wm * 32 + ((lane >> 3) & 1) * 8 + (lane & 7);
    const int a_kb  = (lane >> 4) * 16;
    const int b_nr  = wn * 32 + ((lane >> 4) & 1) * 8 + (lane & 7);
    const int b_kb  = ((lane >> 3) & 1) * 16;
    const int msk   = (lane & 7) << 4;

    if (tid == 0)
        for (int s = 0; s < STAGES; s++) mbar_init(sb + s * 8, 1);
    __syncthreads();
    if (tid == 0) {
        for (int s = 0; s < STAGES; s++) {
            mbar_expect_tx(sb + s * 8, STAGE_BYTES);
            const uint32_t st = sb + S_DATA + s * STAGE_BYTES;
            tma_2d(st,         &tA,  s * 64, m0, sb + s * 8);
            tma_2d(st + 16384, &tB0, s * 64, n0, sb + s * 8);
            tma_2d(st + 24576, &tB1, s * 64, n0, sb + s * 8);
            tma_2d(st + 32768, &tB2, s * 64, n0, sb + s * 8);
        }
    }

    float acc[3][2][4][4];
    #pragma unroll
    for (int m = 0; m < 3; m++)
        #pragma unroll
        for (int i = 0; i < 2; i++)
            #pragma unroll
            for (int j = 0; j < 4; j++)
                #pragma unroll
                for (int r = 0; r < 4; r++) acc[m][i][j][r] = 0.0f;

    for (int kt = 0; kt < 16; kt++) {
        const int s = kt & 1;
        mbar_wait(sb + s * 8, (kt >> 1) & 1);
        const uint32_t uA = sb + S_DATA + s * STAGE_BYTES;

        #pragma unroll
        for (int ks = 0; ks < 4; ks++) {
            const int axk = (ks * 32 + a_kb) ^ msk;
            const int bxk = (ks * 32 + b_kb) ^ msk;
            uint32_t af[2][4];
            ldsm4(af[0], uA + a_r * 128 + axk);
            ldsm4(af[1], uA + (a_r + 16) * 128 + axk);
            #pragma unroll
            for (int mat = 0; mat < 3; mat++) {
                const uint32_t uB = uA + 16384 + mat * 8192 + b_nr * 128;
                uint32_t bb[2][4];
                ldsm4(bb[0], uB + bxk);
                ldsm4(bb[1], uB + 16 * 128 + bxk);
                #pragma unroll
                for (int ns = 0; ns < 4; ns++) {
                    const uint32_t b0 = bb[ns >> 1][(ns & 1) * 2];
                    const uint32_t b1 = bb[ns >> 1][(ns & 1) * 2 + 1];
                    mma16(acc[mat][0][ns], af[0], b0, b1);
                    mma16(acc[mat][1][ns], af[1], b0, b1);
                }
            }
        }
        __syncthreads();
        if (tid == 0 && kt + STAGES < 16) {
            mbar_expect_tx(sb + s * 8, STAGE_BYTES);
            const uint32_t st = sb + S_DATA + s * STAGE_BYTES;
            const int kk = (kt + STAGES) * 64;
            tma_2d(st,         &tA,  kk, m0, sb + s * 8);
            tma_2d(st + 16384, &tB0, kk, n0, sb + s * 8);
            tma_2d(st + 24576, &tB1, kk, n0, sb + s * 8);
            tma_2d(st + 32768, &tB2, kk, n0, sb + s * 8);
        }
    }

    // ---- epilogue: gates in regs -> smem bounce (reuse stage mem) ----
    float* smf = (float*)(smem + S_DATA);              // 128 x EPAD
    float* smv = smf + 128 * EPAD;
    #pragma unroll
    for (int ms = 0; ms < 2; ms++) {
        #pragma unroll
        for (int ns = 0; ns < 4; ns++) {
            const int col = wn * 32 + ns * 8 + gc * 2;
            const float2 Bf = *(const float2*)(bf + n0 + col);
            const float2 Bi = *(const float2*)(bi + n0 + col);
            const float2 Bh = *(const float2*)(bh + n0 + col);
            #pragma unroll
            for (int hf = 0; hf < 2; hf++) {
                const int row = wm * 32 + ms * 16 + gr + hf * 8;
                const float zf0 = acc[0][ms][ns][hf * 2 + 0] + Bf.x;
                const float zf1 = acc[0][ms][ns][hf * 2 + 1] + Bf.y;
                const float zi0 = acc[1][ms][ns][hf * 2 + 0] + Bi.x;
                const float zi1 = acc[1][ms][ns][hf * 2 + 1] + Bi.y;
                const float zh0 = acc[2][ms][ns][hf * 2 + 0] + Bh.x;
                const float zh1 = acc[2][ms][ns][hf * 2 + 1] + Bh.y;
                const float d0 = softplusf(-zf0) - softplusf(-zi0);
                const float d1 = softplusf(-zf1) - softplusf(-zi1);
                const float f0 = sigmf(-d0), f1 = sigmf(-d1);
                const float g0 = (zh0 >= 0.0f) ? (zh0 + 0.5f) : sigmf(zh0);
                const float g1 = (zh1 >= 0.0f) ? (zh1 + 0.5f) : sigmf(zh1);
                *(float2*)(smf + row * EPAD + col) = make_float2(f0, f1);
                *(float2*)(smv + row * EPAD + col) = make_float2(sigmf(d0) * g0, sigmf(d1) * g1);
            }
        }
    }
    __syncthreads();

    // ---- writeout + fused chunk-scan pass 1 (thread = (chunk, col)) ----
    {
        const int ci  = tid >> 6;          // 0..3
        const int col = tid & 63;
        const int b   = m0 >> 12;
        const int cb  = (m0 & 4095) >> 5;
        float F = 1.0f, V = 0.0f;
        float* gf = g_z + (long long)m0 * Hdim + n0 + col;
        float* gv = gf + PLANE;
        #pragma unroll 8
        for (int r = 0; r < 32; r++) {
            const int row = ci * 32 + r;
            const float f = smf[row * EPAD + col];
            const float v = smv[row * EPAD + col];
            V = fmaf(f, V, v);
            F *= f;
            gf[(long long)row * Hdim] = f;
            gv[(long long)row * Hdim] = v;
        }
        const int o = (b * NC + cb + ci) * Hdim + n0 + col;
        g_F[o] = F;
        g_V[o] = V;
    }
}

// ---------------- chunk prefix: warp-parallel affine scan ----------------
__global__ __launch_bounds__(1024)
void chunk_prefix_kernel(const float* __restrict__ h0)
{
    const int g = blockIdx.x * 32 + (threadIdx.x >> 5);
    const int l = threadIdx.x & 31;
    const int b = g >> 10;
    const int h = g & 1023;

    float Fk[4], Vk[4];
    #pragma unroll
    for (int k = 0; k < 4; k++) {
        const int o = (b * NC + 4 * l + k) * Hdim + h;
        Fk[k] = g_F[o];
        Vk[k] = g_V[o];
    }
    float Fa = Fk[0], Va = Vk[0];
    #pragma unroll
    for (int k = 1; k < 4; k++) { Va = fmaf(Fk[k], Va, Vk[k]); Fa *= Fk[k]; }
    #pragma unroll
    for (int d = 1; d < 32; d <<= 1) {
        const float Fo = __shfl_up_sync(0xFFFFFFFF, Fa, d);
        const float Vo = __shfl_up_sync(0xFFFFFFFF, Va, d);
        if (l >= d) { Va = fmaf(Fa, Vo, Va); Fa *= Fo; }
    }
    float Fe = __shfl_up_sync(0xFFFFFFFF, Fa, 1);
    float Ve = __shfl_up_sync(0xFFFFFFFF, Va, 1);
    if (l == 0) { Fe = 1.0f; Ve = 0.0f; }

    const float x = h0[b * Hdim + h];
    const float h0p = (x >= 0.0f) ? (x + 0.5f) : sigmf(x);
    float hs = fmaf(Fe, h0p, Ve);
    #pragma unroll
    for (int k = 0; k < 4; k++) {
        g_Hs[(b * NC + 4 * l + k) * Hdim + h] = hs;
        hs = fmaf(Fk[k], hs, Vk[k]);
    }
}

// ---------------- apply: within-chunk scan, write output ----------------
__global__ __launch_bounds__(1024)
void apply_kernel(float* __restrict__ out)
{
    const int h = threadIdx.x;
    const int c = blockIdx.x;
    const int b = blockIdx.y;
    float run = g_Hs[(b * NC + c) * Hdim + h];
    const float* fp = g_z + ((long long)(b * Tt + c * LCc)) * Hdim + h;
    const float* vp = fp + PLANE;
    float* op = out + ((long long)(b * Tt + c * LCc)) * Hdim + h;
    #pragma unroll 8
    for (int l = 0; l < LCc; l++) {
        const float f = fp[(long long)l * Hdim];
        const float v = vp[(long long)l * Hdim];
        run = fmaf(f, run, v);
        op[(long long)l * Hdim] = run;
    }
}

// ---------------- host ----------------
typedef CUresult (*encode_fn_t)(CUtensorMap*, CUtensorMapDataType, cuuint32_t, void*,
                                const cuuint64_t*, const cuuint64_t*, const cuuint32_t*,
                                const cuuint32_t*, CUtensorMapInterleave, CUtensorMapSwizzle,
                                CUtensorMapL2promotion, CUtensorMapFloatOOBfill);

static void make_map(encode_fn_t enc, CUtensorMap* m, const void* ptr,
                     unsigned long long rows, unsigned box_rows)
{
    cuuint64_t dims[2]    = {1024ull, rows};
    cuuint64_t strides[1] = {2048ull};                 // fp16 row bytes
    cuuint32_t box[2]     = {64u, box_rows};           // 64 halves = 128B = SW128 atom
    cuuint32_t estr[2]    = {1u, 1u};
    enc(m, CU_TENSOR_MAP_DATA_TYPE_FLOAT16, 2, (void*)ptr, dims, strides, box, estr,
        CU_TENSOR_MAP_INTERLEAVE_NONE, CU_TENSOR_MAP_SWIZZLE_128B,
        CU_TENSOR_MAP_L2_PROMOTION_L2_128B, CU_TENSOR_MAP_FLOAT_OOB_FILL_NONE);
}

extern "C" void kernel_launch(void* const* d_in, const int* in_sizes, int n_in,
                              void* d_out, int out_size)
{
    (void)in_sizes; (void)n_in; (void)out_size;
    const float* x  = (const float*)d_in[0];
    const float* h0 = (const float*)d_in[1];
    const float* Wf = (const float*)d_in[2];
    const float* bf = (const float*)d_in[3];
    const float* Wi = (const float*)d_in[4];
    const float* bi = (const float*)d_in[5];
    const float* Wh = (const float*)d_in[6];
    const float* bh = (const float*)d_in[7];
    float* out = (float*)d_out;

    void* xh = nullptr; void* wh = nullptr;
    cudaGetSymbolAddress(&xh, g_xh);
    cudaGetSymbolAddress(&wh, g_wh);

    void* fp = nullptr;
    cudaDriverEntryPointQueryResult qres;
    cudaGetDriverEntryPointByVersion("cuTensorMapEncodeTiled", &fp, 12000,
                                     cudaEnableDefault, &qres);
    encode_fn_t enc = (encode_fn_t)fp;

    CUtensorMap tA, tB0, tB1, tB2;
    make_map(enc, &tA,  xh,                              16384ull, 128u);
    make_map(enc, &tB0, (__half*)wh,                     1024ull,  64u);
    make_map(enc, &tB1, (__half*)wh + 1024 * 1024,       1024ull,  64u);
    make_map(enc, &tB2, (__half*)wh + 2 * 1024 * 1024,   1024ull,  64u);

    cudaFuncSetAttribute(gemm_kernel,
                         cudaFuncAttributeMaxDynamicSharedMemorySize, SMEM_GEMM);

    // launch order arranged so the GEMM is the 4th launch (ncu -s lands there)
    cvt_x_kernel<<<4096, 256>>>((const float4*)x, 0);
    cvt_x_kernel<<<4096, 256>>>((const float4*)x, 1048576);
    cvt_w_kernel<<<512, 256>>>((const float4*)Wf, (const float4*)Wi, (const float4*)Wh);
    gemm_kernel<<<dim3(128, 16), 256, SMEM_GEMM>>>(tA, tB0, tB1, tB2, bf, bi, bh);
    chunk_prefix_kernel<<<128, 1024>>>(h0);
    apply_kernel<<<dim3(NC, Bb), 1024>>>(out);
}

// round 7
// speedup vs baseline: 7.8430x; 1.1949x over previous
#include <cuda_runtime.h>
#include <cuda.h>
#include <cuda_fp16.h>
#include <cstdint>
#include <math.h>

// ---------------- problem constants ----------------
constexpr int Bb = 4, Tt = 4096, Hdim = 1024;
constexpr int Mtot = Bb * Tt;                         // 16384
constexpr long long PLANE = (long long)Mtot * Hdim;   // 16,777,216
constexpr int NC = 128, LCc = 32;
constexpr int EPAD = 66;                              // even pad: float2-aligned smem rows

// Scratch (device globals; allocation-free)
__device__ float g_z[2 * PLANE];                      // plane0 = f, plane1 = v
__device__ __align__(1024) __half g_xh[PLANE];        // fp16 x
__device__ __align__(1024) __half g_wh[3u * 1024 * 1024]; // fp16 Wf|Wi|Wh
__device__ float g_F [Bb * NC * Hdim];
__device__ float g_V [Bb * NC * Hdim];
__device__ float g_Hs[Bb * NC * Hdim];

// ---------------- PTX helpers (base sm_103 target only) ----------------
__device__ __forceinline__ uint32_t smem_u32(const void* p) {
    uint32_t a;
    asm("{ .reg .u64 t; cvta.to.shared.u64 t, %1; cvt.u32.u64 %0, t; }" : "=r"(a) : "l"(p));
    return a;
}
__device__ __forceinline__ void mbar_init(uint32_t a, uint32_t cnt) {
    asm volatile("mbarrier.init.shared.b64 [%0], %1;" :: "r"(a), "r"(cnt) : "memory");
}
__device__ __forceinline__ void mbar_arrive(uint32_t a) {
    asm volatile("mbarrier.arrive.shared.b64 _, [%0];" :: "r"(a) : "memory");
}
__device__ __forceinline__ void mbar_expect_tx(uint32_t a, uint32_t bytes) {
    asm volatile("mbarrier.arrive.expect_tx.shared.b64 _, [%0], %1;" :: "r"(a), "r"(bytes) : "memory");
}
__device__ __forceinline__ void mbar_wait(uint32_t a, uint32_t parity) {
    asm volatile(
        "{\n\t.reg .pred P;\n\t"
        "WL%=:\n\t"
        "mbarrier.try_wait.parity.acquire.cta.shared::cta.b64 P, [%0], %1, 0x989680;\n\t"
        "@!P bra WL%=;\n\t}"
        :: "r"(a), "r"(parity) : "memory");
}
__device__ __forceinline__ void tma_2d(uint32_t dst, const CUtensorMap* m, int x, int y, uint32_t mbar) {
    asm volatile(
        "cp.async.bulk.tensor.2d.shared::cta.global.tile.mbarrier::complete_tx::bytes "
        "[%0], [%1, {%2, %3}], [%4];"
        :: "r"(dst), "l"(m), "r"(x), "r"(y), "r"(mbar) : "memory");
}
__device__ __forceinline__ void ldsm4(uint32_t* r, uint32_t addr) {
    asm volatile("ldmatrix.sync.aligned.m8n8.x4.shared.b16 {%0,%1,%2,%3}, [%4];"
                 : "=r"(r[0]), "=r"(r[1]), "=r"(r[2]), "=r"(r[3]) : "r"(addr));
}
__device__ __forceinline__ void mma16(float* d, const uint32_t* a, uint32_t b0, uint32_t b1) {
    asm volatile(
        "mma.sync.aligned.m16n8k16.row.col.f32.f16.f16.f32 "
        "{%0,%1,%2,%3}, {%4,%5,%6,%7}, {%8,%9}, {%0,%1,%2,%3};"
        : "+f"(d[0]), "+f"(d[1]), "+f"(d[2]), "+f"(d[3])
        : "r"(a[0]), "r"(a[1]), "r"(a[2]), "r"(a[3]), "r"(b0), "r"(b1));
}
__device__ __forceinline__ uint32_t f2h2(float a, float b) {
    __half2 h = __floats2half2_rn(a, b);
    return *reinterpret_cast<uint32_t*>(&h);
}

// ---------------- scalar math ----------------
__device__ __forceinline__ float sigmf(float x) {
    float e = expf(-fabsf(x));
    return (x >= 0.0f) ? 1.0f / (1.0f + e) : e / (1.0f + e);
}

// ---------------- prep: convert inputs to fp16 ----------------
__global__ __launch_bounds__(256)
void cvt_x_kernel(const float4* __restrict__ in, int base) {
    const int g = base + blockIdx.x * 256 + threadIdx.x;   // 8-float groups
    const float4 v0 = in[2 * g];
    const float4 v1 = in[2 * g + 1];
    uint4 o;
    o.x = f2h2(v0.x, v0.y); o.y = f2h2(v0.z, v0.w);
    o.z = f2h2(v1.x, v1.y); o.w = f2h2(v1.z, v1.w);
    ((uint4*)g_xh)[g] = o;
}
__global__ __launch_bounds__(256)
void cvt_w_kernel(const float4* __restrict__ wf, const float4* __restrict__ wi,
                  const float4* __restrict__ wh) {
    const int g = blockIdx.x * 256 + threadIdx.x;          // 131072 groups per mat
    const float4* src[3] = {wf, wi, wh};
    #pragma unroll
    for (int mat = 0; mat < 3; mat++) {
        const float4 v0 = src[mat][2 * g];
        const float4 v1 = src[mat][2 * g + 1];
        uint4 o;
        o.x = f2h2(v0.x, v0.y); o.y = f2h2(v0.z, v0.w);
        o.z = f2h2(v1.x, v1.y); o.w = f2h2(v1.z, v1.w);
        ((uint4*)g_wh)[mat * 131072 + g] = o;
    }
}

// ---------------- fused GEMM (fp16 HMMA) + gates + chunk aggregates ----------------
// CTA: M=128 x N=64, 3 mats. 8 warps (4m x 2n), warp tile 32x32x3.
// 2-stage TMA ring; producer-consumer mbarriers (no per-kt __syncthreads).
constexpr int STAGES = 2;
constexpr int STAGE_BYTES = 40960;                   // A 16K + 3x B 8K
constexpr int S_DATA = 1024;
constexpr int SMEM_GEMM = S_DATA + STAGES * STAGE_BYTES;   // 82,944
static_assert(S_DATA + 2 * 128 * EPAD * 4 <= SMEM_GEMM, "epilogue fits");

__global__ __launch_bounds__(256, 2)
void gemm_kernel(const __grid_constant__ CUtensorMap tA,
                 const __grid_constant__ CUtensorMap tB0,
                 const __grid_constant__ CUtensorMap tB1,
                 const __grid_constant__ CUtensorMap tB2,
                 const float* __restrict__ bf, const float* __restrict__ bi,
                 const float* __restrict__ bh)
{
    extern __shared__ char smem[];
    const uint32_t sb = smem_u32(smem);
    const int tid  = threadIdx.x;
    const int lane = tid & 31;
    const int wid  = tid >> 5;
    const int wm   = wid & 3;          // 0..3
    const int wn   = wid >> 2;         // 0..1
    const int m0   = blockIdx.x * 128;
    const int n0   = blockIdx.y * 64;
    const int gr   = lane >> 2;        // 0..7 (mma D-frag row)
    const int gc   = lane & 3;         // 0..3

    // ldmatrix lane geometry (SW128: addr = row*128 + (colbyte ^ ((row&7)<<4)))
    const int a_r   = wm * 32 + ((lane >> 3) & 1) * 8 + (lane & 7);
    const int a_kb  = (lane >> 4) * 16;
    const int b_nr  = wn * 32 + ((lane >> 4) & 1) * 8 + (lane & 7);
    const int b_kb  = ((lane >> 3) & 1) * 16;
    const int msk   = (lane & 7) << 4;

    // barriers: full[s] at sb+s*16, empty[s] at sb+s*16+8
    if (tid == 0) {
        for (int s = 0; s < STAGES; s++) {
            mbar_init(sb + s * 16, 1);       // full: tx-based
            mbar_init(sb + s * 16 + 8, 8);   // empty: one arrive per warp
        }
    }
    __syncthreads();
    if (tid == 0) {
        for (int s = 0; s < STAGES; s++) {
            mbar_expect_tx(sb + s * 16, STAGE_BYTES);
            const uint32_t st = sb + S_DATA + s * STAGE_BYTES;
            tma_2d(st,         &tA,  s * 64, m0, sb + s * 16);
            tma_2d(st + 16384, &tB0, s * 64, n0, sb + s * 16);
            tma_2d(st + 24576, &tB1, s * 64, n0, sb + s * 16);
            tma_2d(st + 32768, &tB2, s * 64, n0, sb + s * 16);
        }
    }

    float acc[3][2][4][4];
    #pragma unroll
    for (int m = 0; m < 3; m++)
        #pragma unroll
        for (int i = 0; i < 2; i++)
            #pragma unroll
            for (int j = 0; j < 4; j++)
                #pragma unroll
                for (int r = 0; r < 4; r++) acc[m][i][j][r] = 0.0f;

    const uint32_t stg0 = sb + S_DATA;
    const uint32_t stg1 = sb + S_DATA + STAGE_BYTES;

    for (int kt = 0; kt < 16; kt++) {
        const int s  = kt & 1;
        const int ph = (kt >> 1) & 1;
        mbar_wait(sb + s * 16, ph);
        const uint32_t uA = s ? stg1 : stg0;

        #pragma unroll
        for (int ks = 0; ks < 4; ks++) {
            const int axk = (ks * 32 + a_kb) ^ msk;
            const int bxk = (ks * 32 + b_kb) ^ msk;
            uint32_t af[2][4];
            ldsm4(af[0], uA + a_r * 128 + axk);
            ldsm4(af[1], uA + (a_r + 16) * 128 + axk);
            #pragma unroll
            for (int mat = 0; mat < 3; mat++) {
                const uint32_t uB = uA + 16384 + mat * 8192 + b_nr * 128;
                uint32_t bb[2][4];
                ldsm4(bb[0], uB + bxk);
                ldsm4(bb[1], uB + 16 * 128 + bxk);
                #pragma unroll
                for (int ns = 0; ns < 4; ns++) {
                    const uint32_t b0 = bb[ns >> 1][(ns & 1) * 2];
                    const uint32_t b1 = bb[ns >> 1][(ns & 1) * 2 + 1];
                    mma16(acc[mat][0][ns], af[0], b0, b1);
                    mma16(acc[mat][1][ns], af[1], b0, b1);
                }
            }
        }
        __syncwarp();
        if (lane == 0) mbar_arrive(sb + s * 16 + 8);   // this warp done with stage s

        if (tid == 0 && kt + STAGES < 16) {
            mbar_wait(sb + s * 16 + 8, ph);            // all 8 warps released stage s
            mbar_expect_tx(sb + s * 16, STAGE_BYTES);
            const uint32_t st = s ? stg1 : stg0;
            const int kk = (kt + STAGES) * 64;
            tma_2d(st,         &tA,  kk, m0, sb + s * 16);
            tma_2d(st + 16384, &tB0, kk, n0, sb + s * 16);
            tma_2d(st + 24576, &tB1, kk, n0, sb + s * 16);
            tma_2d(st + 32768, &tB2, kk, n0, sb + s * 16);
        }
    }
    __syncthreads();   // all warps out of mainloop before stage smem is reused

    // ---- epilogue: gates in regs -> smem bounce (reuse stage mem) ----
    // f = (1+e^-zi)/(2+e^-zf+e^-zi), i = (1+e^-zf)/same, g = zh>=0? zh+0.5 : sigm(zh)
    float* smf = (float*)(smem + S_DATA);              // 128 x EPAD
    float* smv = smf + 128 * EPAD;
    #pragma unroll
    for (int ms = 0; ms < 2; ms++) {
        #pragma unroll
        for (int ns = 0; ns < 4; ns++) {
            const int col = wn * 32 + ns * 8 + gc * 2;
            const float2 Bf = *(const float2*)(bf + n0 + col);
            const float2 Bi = *(const float2*)(bi + n0 + col);
            const float2 Bh = *(const float2*)(bh + n0 + col);
            #pragma unroll
            for (int hf = 0; hf < 2; hf++) {
                const int row = wm * 32 + ms * 16 + gr + hf * 8;
                #pragma unroll
                for (int e = 0; e < 2; e++) {
                    const float zf = acc[0][ms][ns][hf * 2 + e] + (e ? Bf.y : Bf.x);
                    const float zi = acc[1][ms][ns][hf * 2 + e] + (e ? Bi.y : Bi.x);
                    const float zh = acc[2][ms][ns][hf * 2 + e] + (e ? Bh.y : Bh.x);
                    const float a  = __expf(-zf);
                    const float b  = __expf(-zi);
                    const float rd = __fdividef(1.0f, 2.0f + a + b);
                    const float f  = (1.0f + b) * rd;
                    const float c  = __expf(zh);
                    const float gneg = __fdividef(c, 1.0f + c);
                    const float gg = (zh >= 0.0f) ? (zh + 0.5f) : gneg;
                    const float v  = (1.0f + a) * rd * gg;
                    smf[row * EPAD + col + e] = f;
                    smv[row * EPAD + col + e] = v;
                }
            }
        }
    }
    __syncthreads();

    // ---- writeout + fused chunk-scan pass 1 (thread = (chunk, col)) ----
    {
        const int ci  = tid >> 6;          // 0..3
        const int col = tid & 63;
        const int b   = m0 >> 12;
        const int cb  = (m0 & 4095) >> 5;
        float F = 1.0f, V = 0.0f;
        float* gf = g_z + (long long)m0 * Hdim + n0 + col;
        float* gv = gf + PLANE;
        #pragma unroll 8
        for (int r = 0; r < 32; r++) {
            const int row = ci * 32 + r;
            const float f = smf[row * EPAD + col];
            const float v = smv[row * EPAD + col];
            V = fmaf(f, V, v);
            F *= f;
            gf[(long long)row * Hdim] = f;
            gv[(long long)row * Hdim] = v;
        }
        const int o = (b * NC + cb + ci) * Hdim + n0 + col;
        g_F[o] = F;
        g_V[o] = V;
    }
}

// ---------------- chunk prefix: warp-parallel affine scan ----------------
__global__ __launch_bounds__(1024)
void chunk_prefix_kernel(const float* __restrict__ h0)
{
    const int g = blockIdx.x * 32 + (threadIdx.x >> 5);
    const int l = threadIdx.x & 31;
    const int b = g >> 10;
    const int h = g & 1023;

    float Fk[4], Vk[4];
    #pragma unroll
    for (int k = 0; k < 4; k++) {
        const int o = (b * NC + 4 * l + k) * Hdim + h;
        Fk[k] = g_F[o];
        Vk[k] = g_V[o];
    }
    float Fa = Fk[0], Va = Vk[0];
    #pragma unroll
    for (int k = 1; k < 4; k++) { Va = fmaf(Fk[k], Va, Vk[k]); Fa *= Fk[k]; }
    #pragma unroll
    for (int d = 1; d < 32; d <<= 1) {
        const float Fo = __shfl_up_sync(0xFFFFFFFF, Fa, d);
        const float Vo = __shfl_up_sync(0xFFFFFFFF, Va, d);
        if (l >= d) { Va = fmaf(Fa, Vo, Va); Fa *= Fo; }
    }
    float Fe = __shfl_up_sync(0xFFFFFFFF, Fa, 1);
    float Ve = __shfl_up_sync(0xFFFFFFFF, Va, 1);
    if (l == 0) { Fe = 1.0f; Ve = 0.0f; }

    const float x = h0[b * Hdim + h];
    const float h0p = (x >= 0.0f) ? (x + 0.5f) : sigmf(x);
    float hs = fmaf(Fe, h0p, Ve);
    #pragma unroll
    for (int k = 0; k < 4; k++) {
        g_Hs[(b * NC + 4 * l + k) * Hdim + h] = hs;
        hs = fmaf(Fk[k], hs, Vk[k]);
    }
}

// ---------------- apply: within-chunk scan, write output ----------------
__global__ __launch_bounds__(1024)
void apply_kernel(float* __restrict__ out)
{
    const int h = threadIdx.x;
    const int c = blockIdx.x;
    const int b = blockIdx.y;
    float run = g_Hs[(b * NC + c) * Hdim + h];
    const float* fp = g_z + ((long long)(b * Tt + c * LCc)) * Hdim + h;
    const float* vp = fp + PLANE;
    float* op = out + ((long long)(b * Tt + c * LCc)) * Hdim + h;
    #pragma unroll 8
    for (int l = 0; l < LCc; l++) {
        const float f = fp[(long long)l * Hdim];
        const float v = vp[(long long)l * Hdim];
        run = fmaf(f, run, v);
        op[(long long)l * Hdim] = run;
    }
}

// ---------------- host ----------------
typedef CUresult (*encode_fn_t)(CUtensorMap*, CUtensorMapDataType, cuuint32_t, void*,
                                const cuuint64_t*, const cuuint64_t*, const cuuint32_t*,
                                const cuuint32_t*, CUtensorMapInterleave, CUtensorMapSwizzle,
                                CUtensorMapL2promotion, CUtensorMapFloatOOBfill);

static void make_map(encode_fn_t enc, CUtensorMap* m, const void* ptr,
                     unsigned long long rows, unsigned box_rows)
{
    cuuint64_t dims[2]    = {1024ull, rows};
    cuuint64_t strides[1] = {2048ull};                 // fp16 row bytes
    cuuint32_t box[2]     = {64u, box_rows};           // 64 halves = 128B = SW128 atom
    cuuint32_t estr[2]    = {1u, 1u};
    enc(m, CU_TENSOR_MAP_DATA_TYPE_FLOAT16, 2, (void*)ptr, dims, strides, box, estr,
        CU_TENSOR_MAP_INTERLEAVE_NONE, CU_TENSOR_MAP_SWIZZLE_128B,
        CU_TENSOR_MAP_L2_PROMOTION_L2_128B, CU_TENSOR_MAP_FLOAT_OOB_FILL_NONE);
}

extern "C" void kernel_launch(void* const* d_in, const int* in_sizes, int n_in,
                              void* d_out, int out_size)
{
    (void)in_sizes; (void)n_in; (void)out_size;
    const float* x  = (const float*)d_in[0];
    const float* h0 = (const float*)d_in[1];
    const float* Wf = (const float*)d_in[2];
    const float* bf = (const float*)d_in[3];
    const float* Wi = (const float*)d_in[4];
    const float* bi = (const float*)d_in[5];
    const float* Wh = (const float*)d_in[6];
    const float* bh = (const float*)d_in[7];
    float* out = (float*)d_out;

    void* xh = nullptr; void* wh = nullptr;
    cudaGetSymbolAddress(&xh, g_xh);
    cudaGetSymbolAddress(&wh, g_wh);

    void* fp = nullptr;
    cudaDriverEntryPointQueryResult qres;
    cudaGetDriverEntryPointByVersion("cuTensorMapEncodeTiled", &fp, 12000,
                                     cudaEnableDefault, &qres);
    encode_fn_t enc = (encode_fn_t)fp;

    CUtensorMap tA, tB0, tB1, tB2;
    make_map(enc, &tA,  xh,                              16384ull, 128u);
    make_map(enc, &tB0, (__half*)wh,                     1024ull,  64u);
    make_map(enc, &tB1, (__half*)wh + 1024 * 1024,       1024ull,  64u);
    make_map(enc, &tB2, (__half*)wh + 2 * 1024 * 1024,   1024ull,  64u);

    cudaFuncSetAttribute(gemm_kernel,
                         cudaFuncAttributeMaxDynamicSharedMemorySize, SMEM_GEMM);

    // launch order: GEMM is 4th launch (ncu -s 5 -c 1 lands there)
    cvt_x_kernel<<<4096, 256>>>((const float4*)x, 0);
    cvt_x_kernel<<<4096, 256>>>((const float4*)x, 1048576);
    cvt_w_kernel<<<512, 256>>>((const float4*)Wf, (const float4*)Wi, (const float4*)Wh);
    gemm_kernel<<<dim3(128, 16), 256, SMEM_GEMM>>>(tA, tB0, tB1, tB2, bf, bi, bh);
    chunk_prefix_kernel<<<128, 1024>>>(h0);
    apply_kernel<<<dim3(NC, Bb), 1024>>>(out);
}

// round 8
// speedup vs baseline: 7.8530x; 1.0013x over previous
#include <cuda_runtime.h>
#include <cuda.h>
#include <cuda_fp16.h>
#include <cstdint>
#include <math.h>

// ---------------- problem constants ----------------
constexpr int Bb = 4, Tt = 4096, Hdim = 1024;
constexpr int Mtot = Bb * Tt;                         // 16384
constexpr long long PLANE = (long long)Mtot * Hdim;   // 16,777,216
constexpr int NC = 128, LCc = 32;
constexpr int EPAD = 66;                              // even pad

// Scratch (device globals; allocation-free)
__device__ __align__(16) __half2 g_fv[PLANE];         // packed (f, v) per element
__device__ __align__(1024) __half g_xh[PLANE];        // fp16 x
__device__ __align__(1024) __half g_wh[3u * 1024 * 1024]; // fp16 Wf|Wi|Wh
__device__ float g_F [Bb * NC * Hdim];
__device__ float g_V [Bb * NC * Hdim];
__device__ float g_Hs[Bb * NC * Hdim];

// ---------------- PTX helpers (base sm_103 target only) ----------------
__device__ __forceinline__ uint32_t smem_u32(const void* p) {
    uint32_t a;
    asm("{ .reg .u64 t; cvta.to.shared.u64 t, %1; cvt.u32.u64 %0, t; }" : "=r"(a) : "l"(p));
    return a;
}
__device__ __forceinline__ void mbar_init(uint32_t a, uint32_t cnt) {
    asm volatile("mbarrier.init.shared.b64 [%0], %1;" :: "r"(a), "r"(cnt) : "memory");
}
__device__ __forceinline__ void mbar_arrive(uint32_t a) {
    asm volatile("mbarrier.arrive.shared.b64 _, [%0];" :: "r"(a) : "memory");
}
__device__ __forceinline__ void mbar_expect_tx(uint32_t a, uint32_t bytes) {
    asm volatile("mbarrier.arrive.expect_tx.shared.b64 _, [%0], %1;" :: "r"(a), "r"(bytes) : "memory");
}
__device__ __forceinline__ void mbar_wait(uint32_t a, uint32_t parity) {
    asm volatile(
        "{\n\t.reg .pred P;\n\t"
        "WL%=:\n\t"
        "mbarrier.try_wait.parity.acquire.cta.shared::cta.b64 P, [%0], %1, 0x989680;\n\t"
        "@!P bra WL%=;\n\t}"
        :: "r"(a), "r"(parity) : "memory");
}
__device__ __forceinline__ void tma_2d(uint32_t dst, const CUtensorMap* m, int x, int y, uint32_t mbar) {
    asm volatile(
        "cp.async.bulk.tensor.2d.shared::cta.global.tile.mbarrier::complete_tx::bytes "
        "[%0], [%1, {%2, %3}], [%4];"
        :: "r"(dst), "l"(m), "r"(x), "r"(y), "r"(mbar) : "memory");
}
__device__ __forceinline__ void ldsm4(uint32_t* r, uint32_t addr) {
    asm volatile("ldmatrix.sync.aligned.m8n8.x4.shared.b16 {%0,%1,%2,%3}, [%4];"
                 : "=r"(r[0]), "=r"(r[1]), "=r"(r[2]), "=r"(r[3]) : "r"(addr));
}
__device__ __forceinline__ void mma16(float* d, const uint32_t* a, uint32_t b0, uint32_t b1) {
    asm volatile(
        "mma.sync.aligned.m16n8k16.row.col.f32.f16.f16.f32 "
        "{%0,%1,%2,%3}, {%4,%5,%6,%7}, {%8,%9}, {%0,%1,%2,%3};"
        : "+f"(d[0]), "+f"(d[1]), "+f"(d[2]), "+f"(d[3])
        : "r"(a[0]), "r"(a[1]), "r"(a[2]), "r"(a[3]), "r"(b0), "r"(b1));
}
__device__ __forceinline__ uint32_t f2h2(float a, float b) {
    __half2 h = __floats2half2_rn(a, b);
    return *reinterpret_cast<uint32_t*>(&h);
}

// ---------------- scalar math ----------------
__device__ __forceinline__ float sigmf(float x) {
    float e = expf(-fabsf(x));
    return (x >= 0.0f) ? 1.0f / (1.0f + e) : e / (1.0f + e);
}

// ---------------- prep: convert inputs to fp16 ----------------
__global__ __launch_bounds__(256)
void cvt_x_kernel(const float4* __restrict__ in, int base) {
    const int g = base + blockIdx.x * 256 + threadIdx.x;   // 8-float groups
    const float4 v0 = in[2 * g];
    const float4 v1 = in[2 * g + 1];
    uint4 o;
    o.x = f2h2(v0.x, v0.y); o.y = f2h2(v0.z, v0.w);
    o.z = f2h2(v1.x, v1.y); o.w = f2h2(v1.z, v1.w);
    ((uint4*)g_xh)[g] = o;
}
__global__ __launch_bounds__(256)
void cvt_w_kernel(const float4* __restrict__ wf, const float4* __restrict__ wi,
                  const float4* __restrict__ wh) {
    const int g = blockIdx.x * 256 + threadIdx.x;          // 131072 groups per mat
    const float4* src[3] = {wf, wi, wh};
    #pragma unroll
    for (int mat = 0; mat < 3; mat++) {
        const float4 v0 = src[mat][2 * g];
        const float4 v1 = src[mat][2 * g + 1];
        uint4 o;
        o.x = f2h2(v0.x, v0.y); o.y = f2h2(v0.z, v0.w);
        o.z = f2h2(v1.x, v1.y); o.w = f2h2(v1.z, v1.w);
        ((uint4*)g_wh)[mat * 131072 + g] = o;
    }
}

// ---------------- fused GEMM (fp16 HMMA) + gates + chunk aggregates ----------------
constexpr int STAGES = 2;
constexpr int STAGE_BYTES = 40960;                   // A 16K + 3x B 8K
constexpr int S_DATA = 1024;
constexpr int SMEM_GEMM = S_DATA + STAGES * STAGE_BYTES;   // 82,944
static_assert(S_DATA + 128 * EPAD * 4 <= SMEM_GEMM, "epilogue fits");

__global__ __launch_bounds__(256, 2)
void gemm_kernel(const __grid_constant__ CUtensorMap tA,
                 const __grid_constant__ CUtensorMap tB0,
                 const __grid_constant__ CUtensorMap tB1,
                 const __grid_constant__ CUtensorMap tB2,
                 const float* __restrict__ bf, const float* __restrict__ bi,
                 const float* __restrict__ bh)
{
    extern __shared__ char smem[];
    const uint32_t sb = smem_u32(smem);
    const int tid  = threadIdx.x;
    const int lane = tid & 31;
    const int wid  = tid >> 5;
    const int wm   = wid & 3;          // 0..3
    const int wn   = wid >> 2;         // 0..1
    const int m0   = blockIdx.x * 128;
    const int n0   = blockIdx.y * 64;
    const int gr   = lane >> 2;        // 0..7
    const int gc   = lane & 3;         // 0..3

    // ldmatrix lane geometry (SW128: addr = row*128 + (colbyte ^ ((row&7)<<4)))
    const int a_r   = wm * 32 + ((lane >> 3) & 1) * 8 + (lane & 7);
    const int a_kb  = (lane >> 4) * 16;
    const int b_nr  = wn * 32 + ((lane >> 4) & 1) * 8 + (lane & 7);
    const int b_kb  = ((lane >> 3) & 1) * 16;
    const int msk   = (lane & 7) << 4;

    // barriers: full[s] at sb+s*16, empty[s] at sb+s*16+8
    if (tid == 0) {
        for (int s = 0; s < STAGES; s++) {
            mbar_init(sb + s * 16, 1);       // full: tx-based
            mbar_init(sb + s * 16 + 8, 8);   // empty: one arrive per warp
        }
    }
    __syncthreads();
    if (tid == 0) {
        for (int s = 0; s < STAGES; s++) {
            mbar_expect_tx(sb + s * 16, STAGE_BYTES);
            const uint32_t st = sb + S_DATA + s * STAGE_BYTES;
            tma_2d(st,         &tA,  s * 64, m0, sb + s * 16);
            tma_2d(st + 16384, &tB0, s * 64, n0, sb + s * 16);
            tma_2d(st + 24576, &tB1, s * 64, n0, sb + s * 16);
            tma_2d(st + 32768, &tB2, s * 64, n0, sb + s * 16);
        }
    }

    float acc[3][2][4][4];
    #pragma unroll
    for (int m = 0; m < 3; m++)
        #pragma unroll
        for (int i = 0; i < 2; i++)
            #pragma unroll
            for (int j = 0; j < 4; j++)
                #pragma unroll
                for (int r = 0; r < 4; r++) acc[m][i][j][r] = 0.0f;

    const uint32_t stg0 = sb + S_DATA;
    const uint32_t stg1 = sb + S_DATA + STAGE_BYTES;

    for (int kt = 0; kt < 16; kt++) {
        const int s  = kt & 1;
        const int ph = (kt >> 1) & 1;
        mbar_wait(sb + s * 16, ph);
        const uint32_t uA = s ? stg1 : stg0;

        #pragma unroll
        for (int ks = 0; ks < 4; ks++) {
            const int axk = (ks * 32 + a_kb) ^ msk;
            const int bxk = (ks * 32 + b_kb) ^ msk;
            uint32_t af[2][4];
            ldsm4(af[0], uA + a_r * 128 + axk);
            ldsm4(af[1], uA + (a_r + 16) * 128 + axk);
            #pragma unroll
            for (int mat = 0; mat < 3; mat++) {
                const uint32_t uB = uA + 16384 + mat * 8192 + b_nr * 128;
                uint32_t bb[2][4];
                ldsm4(bb[0], uB + bxk);
                ldsm4(bb[1], uB + 16 * 128 + bxk);
                #pragma unroll
                for (int ns = 0; ns < 4; ns++) {
                    const uint32_t b0 = bb[ns >> 1][(ns & 1) * 2];
                    const uint32_t b1 = bb[ns >> 1][(ns & 1) * 2 + 1];
                    mma16(acc[mat][0][ns], af[0], b0, b1);
                    mma16(acc[mat][1][ns], af[1], b0, b1);
                }
            }
        }
        __syncwarp();
        if (lane == 0) mbar_arrive(sb + s * 16 + 8);   // warp done with stage s

        if (tid == 0 && kt + STAGES < 16) {
            mbar_wait(sb + s * 16 + 8, ph);            // all warps released stage s
            mbar_expect_tx(sb + s * 16, STAGE_BYTES);
            const uint32_t st = s ? stg1 : stg0;
            const int kk = (kt + STAGES) * 64;
            tma_2d(st,         &tA,  kk, m0, sb + s * 16);
            tma_2d(st + 16384, &tB0, kk, n0, sb + s * 16);
            tma_2d(st + 24576, &tB1, kk, n0, sb + s * 16);
            tma_2d(st + 32768, &tB2, kk, n0, sb + s * 16);
        }
    }
    __syncthreads();   // all warps done before stage smem reuse

    // ---- epilogue: gates in regs -> packed half2 smem bounce ----
    __half2* smfv = (__half2*)(smem + S_DATA);         // 128 x EPAD half2
    #pragma unroll
    for (int ms = 0; ms < 2; ms++) {
        #pragma unroll
        for (int ns = 0; ns < 4; ns++) {
            const int col = wn * 32 + ns * 8 + gc * 2;
            const float2 Bf = *(const float2*)(bf + n0 + col);
            const float2 Bi = *(const float2*)(bi + n0 + col);
            const float2 Bh = *(const float2*)(bh + n0 + col);
            #pragma unroll
            for (int hf = 0; hf < 2; hf++) {
                const int row = wm * 32 + ms * 16 + gr + hf * 8;
                #pragma unroll
                for (int e = 0; e < 2; e++) {
                    const float zf = acc[0][ms][ns][hf * 2 + e] + (e ? Bf.y : Bf.x);
                    const float zi = acc[1][ms][ns][hf * 2 + e] + (e ? Bi.y : Bi.x);
                    const float zh = acc[2][ms][ns][hf * 2 + e] + (e ? Bh.y : Bh.x);
                    const float a  = __expf(-zf);
                    const float b  = __expf(-zi);
                    const float rd = __fdividef(1.0f, 2.0f + a + b);
                    const float f  = (1.0f + b) * rd;
                    const float c  = __expf(zh);
                    const float gg = (zh >= 0.0f) ? (zh + 0.5f) : __fdividef(c, 1.0f + c);
                    const float v  = (1.0f + a) * rd * gg;
                    smfv[row * EPAD + col + e] = __floats2half2_rn(f, v);
                }
            }
        }
    }
    __syncthreads();

    // ---- writeout + fused chunk-scan pass 1 (thread = (chunk, col)) ----
    {
        const int ci  = tid >> 6;          // 0..3
        const int col = tid & 63;
        const int b   = m0 >> 12;
        const int cb  = (m0 & 4095) >> 5;
        float F = 1.0f, V = 0.0f;
        __half2* gfv = g_fv + (long long)m0 * Hdim + n0 + col;
        #pragma unroll 8
        for (int r = 0; r < 32; r++) {
            const int row = ci * 32 + r;
            const __half2 p = smfv[row * EPAD + col];
            const float2 fv = __half22float2(p);
            V = fmaf(fv.x, V, fv.y);
            F *= fv.x;
            gfv[(long long)row * Hdim] = p;
        }
        const int o = (b * NC + cb + ci) * Hdim + n0 + col;
        g_F[o] = F;
        g_V[o] = V;
    }
}

// ---------------- chunk prefix: warp-parallel affine scan ----------------
__global__ __launch_bounds__(1024)
void chunk_prefix_kernel(const float* __restrict__ h0)
{
    const int g = blockIdx.x * 32 + (threadIdx.x >> 5);
    const int l = threadIdx.x & 31;
    const int b = g >> 10;
    const int h = g & 1023;

    float Fk[4], Vk[4];
    #pragma unroll
    for (int k = 0; k < 4; k++) {
        const int o = (b * NC + 4 * l + k) * Hdim + h;
        Fk[k] = g_F[o];
        Vk[k] = g_V[o];
    }
    float Fa = Fk[0], Va = Vk[0];
    #pragma unroll
    for (int k = 1; k < 4; k++) { Va = fmaf(Fk[k], Va, Vk[k]); Fa *= Fk[k]; }
    #pragma unroll
    for (int d = 1; d < 32; d <<= 1) {
        const float Fo = __shfl_up_sync(0xFFFFFFFF, Fa, d);
        const float Vo = __shfl_up_sync(0xFFFFFFFF, Va, d);
        if (l >= d) { Va = fmaf(Fa, Vo, Va); Fa *= Fo; }
    }
    float Fe = __shfl_up_sync(0xFFFFFFFF, Fa, 1);
    float Ve = __shfl_up_sync(0xFFFFFFFF, Va, 1);
    if (l == 0) { Fe = 1.0f; Ve = 0.0f; }

    const float x = h0[b * Hdim + h];
    const float h0p = (x >= 0.0f) ? (x + 0.5f) : sigmf(x);
    float hs = fmaf(Fe, h0p, Ve);
    #pragma unroll
    for (int k = 0; k < 4; k++) {
        g_Hs[(b * NC + 4 * l + k) * Hdim + h] = hs;
        hs = fmaf(Fk[k], hs, Vk[k]);
    }
}

// ---------------- apply: within-chunk scan, write output ----------------
__global__ __launch_bounds__(1024)
void apply_kernel(float* __restrict__ out)
{
    const int h = threadIdx.x;
    const int c = blockIdx.x;
    const int b = blockIdx.y;
    float run = g_Hs[(b * NC + c) * Hdim + h];
    const __half2* fvp = g_fv + ((long long)(b * Tt + c * LCc)) * Hdim + h;
    float* op = out + ((long long)(b * Tt + c * LCc)) * Hdim + h;
    #pragma unroll 8
    for (int l = 0; l < LCc; l++) {
        const float2 fv = __half22float2(fvp[(long long)l * Hdim]);
        run = fmaf(fv.x, run, fv.y);
        op[(long long)l * Hdim] = run;
    }
}

// ---------------- host ----------------
typedef CUresult (*encode_fn_t)(CUtensorMap*, CUtensorMapDataType, cuuint32_t, void*,
                                const cuuint64_t*, const cuuint64_t*, const cuuint32_t*,
                                const cuuint32_t*, CUtensorMapInterleave, CUtensorMapSwizzle,
                                CUtensorMapL2promotion, CUtensorMapFloatOOBfill);

static void make_map(encode_fn_t enc, CUtensorMap* m, const void* ptr,
                     unsigned long long rows, unsigned box_rows)
{
    cuuint64_t dims[2]    = {1024ull, rows};
    cuuint64_t strides[1] = {2048ull};                 // fp16 row bytes
    cuuint32_t box[2]     = {64u, box_rows};           // 64 halves = 128B = SW128 atom
    cuuint32_t estr[2]    = {1u, 1u};
    enc(m, CU_TENSOR_MAP_DATA_TYPE_FLOAT16, 2, (void*)ptr, dims, strides, box, estr,
        CU_TENSOR_MAP_INTERLEAVE_NONE, CU_TENSOR_MAP_SWIZZLE_128B,
        CU_TENSOR_MAP_L2_PROMOTION_L2_128B, CU_TENSOR_MAP_FLOAT_OOB_FILL_NONE);
}

extern "C" void kernel_launch(void* const* d_in, const int* in_sizes, int n_in,
                              void* d_out, int out_size)
{
    (void)in_sizes; (void)n_in; (void)out_size;
    const float* x  = (const float*)d_in[0];
    const float* h0 = (const float*)d_in[1];
    const float* Wf = (const float*)d_in[2];
    const float* bf = (const float*)d_in[3];
    const float* Wi = (const float*)d_in[4];
    const float* bi = (const float*)d_in[5];
    const float* Wh = (const float*)d_in[6];
    const float* bh = (const float*)d_in[7];
    float* out = (float*)d_out;

    void* xh = nullptr; void* wh = nullptr;
    cudaGetSymbolAddress(&xh, g_xh);
    cudaGetSymbolAddress(&wh, g_wh);

    void* fp = nullptr;
    cudaDriverEntryPointQueryResult qres;
    cudaGetDriverEntryPointByVersion("cuTensorMapEncodeTiled", &fp, 12000,
                                     cudaEnableDefault, &qres);
    encode_fn_t enc = (encode_fn_t)fp;

    CUtensorMap tA, tB0, tB1, tB2;
    make_map(enc, &tA,  xh,                              16384ull, 128u);
    make_map(enc, &tB0, (__half*)wh,                     1024ull,  64u);
    make_map(enc, &tB1, (__half*)wh + 1024 * 1024,       1024ull,  64u);
    make_map(enc, &tB2, (__half*)wh + 2 * 1024 * 1024,   1024ull,  64u);

    cudaFuncSetAttribute(gemm_kernel,
                         cudaFuncAttributeMaxDynamicSharedMemorySize, SMEM_GEMM);

    // launch order: GEMM is 4th launch (ncu -s 5 -c 1 lands there)
    cvt_x_kernel<<<4096, 256>>>((const float4*)x, 0);
    cvt_x_kernel<<<4096, 256>>>((const float4*)x, 1048576);
    cvt_w_kernel<<<512, 256>>>((const float4*)Wf, (const float4*)Wi, (const float4*)Wh);
    gemm_kernel<<<dim3(128, 16), 256, SMEM_GEMM>>>(tA, tB0, tB1, tB2, bf, bi, bh);
    chunk_prefix_kernel<<<128, 1024>>>(h0);
    apply_kernel<<<dim3(NC, Bb), 1024>>>(out);
}

// round 9
// speedup vs baseline: 8.1320x; 1.0355x over previous
#include <cuda_runtime.h>
#include <cuda.h>
#include <cuda_fp16.h>
#include <cstdint>
#include <math.h>

// ---------------- problem constants ----------------
constexpr int Bb = 4, Tt = 4096, Hdim = 1024;
constexpr int Mtot = Bb * Tt;                         // 16384
constexpr long long PLANE = (long long)Mtot * Hdim;   // 16,777,216
constexpr int NC = 128, LCc = 32;
constexpr int EPAD = 66;                              // even pad

// Scratch (device globals; allocation-free)
__device__ __align__(16) __half2 g_fv[PLANE];         // packed (f, v) per element
__device__ __align__(1024) __half g_xh[PLANE];        // fp16 x
__device__ __align__(1024) __half g_wh[3u * 1024 * 1024]; // fp16 Wf|Wi|Wh
__device__ float g_F [Bb * NC * Hdim];
__device__ float g_V [Bb * NC * Hdim];
__device__ float g_Hs[Bb * NC * Hdim];

// ---------------- PTX helpers (base sm_103 target only) ----------------
__device__ __forceinline__ uint32_t smem_u32(const void* p) {
    uint32_t a;
    asm("{ .reg .u64 t; cvta.to.shared.u64 t, %1; cvt.u32.u64 %0, t; }" : "=r"(a) : "l"(p));
    return a;
}
__device__ __forceinline__ void mbar_init(uint32_t a, uint32_t cnt) {
    asm volatile("mbarrier.init.shared.b64 [%0], %1;" :: "r"(a), "r"(cnt) : "memory");
}
__device__ __forceinline__ void mbar_arrive(uint32_t a) {
    asm volatile("mbarrier.arrive.shared.b64 _, [%0];" :: "r"(a) : "memory");
}
__device__ __forceinline__ void mbar_expect_tx(uint32_t a, uint32_t bytes) {
    asm volatile("mbarrier.arrive.expect_tx.shared.b64 _, [%0], %1;" :: "r"(a), "r"(bytes) : "memory");
}
__device__ __forceinline__ void mbar_wait(uint32_t a, uint32_t parity) {
    asm volatile(
        "{\n\t.reg .pred P;\n\t"
        "WL%=:\n\t"
        "mbarrier.try_wait.parity.acquire.cta.shared::cta.b64 P, [%0], %1, 0x989680;\n\t"
        "@!P bra WL%=;\n\t}"
        :: "r"(a), "r"(parity) : "memory");
}
__device__ __forceinline__ void tma_2d(uint32_t dst, const CUtensorMap* m, int x, int y, uint32_t mbar) {
    asm volatile(
        "cp.async.bulk.tensor.2d.shared::cta.global.tile.mbarrier::complete_tx::bytes "
        "[%0], [%1, {%2, %3}], [%4];"
        :: "r"(dst), "l"(m), "r"(x), "r"(y), "r"(mbar) : "memory");
}
__device__ __forceinline__ void ldsm4(uint32_t* r, uint32_t addr) {
    asm volatile("ldmatrix.sync.aligned.m8n8.x4.shared.b16 {%0,%1,%2,%3}, [%4];"
                 : "=r"(r[0]), "=r"(r[1]), "=r"(r[2]), "=r"(r[3]) : "r"(addr));
}
__device__ __forceinline__ void mma16(float* d, const uint32_t* a, uint32_t b0, uint32_t b1) {
    asm volatile(
        "mma.sync.aligned.m16n8k16.row.col.f32.f16.f16.f32 "
        "{%0,%1,%2,%3}, {%4,%5,%6,%7}, {%8,%9}, {%0,%1,%2,%3};"
        : "+f"(d[0]), "+f"(d[1]), "+f"(d[2]), "+f"(d[3])
        : "r"(a[0]), "r"(a[1]), "r"(a[2]), "r"(a[3]), "r"(b0), "r"(b1));
}
__device__ __forceinline__ uint32_t f2h2(float a, float b) {
    __half2 h = __floats2half2_rn(a, b);
    return *reinterpret_cast<uint32_t*>(&h);
}

// ---------------- scalar math ----------------
__device__ __forceinline__ float sigmf(float x) {
    float e = expf(-fabsf(x));
    return (x >= 0.0f) ? 1.0f / (1.0f + e) : e / (1.0f + e);
}

// ---------------- prep: convert inputs to fp16 ----------------
__global__ __launch_bounds__(256)
void cvt_x_kernel(const float4* __restrict__ in, int base) {
    const int g = base + blockIdx.x * 256 + threadIdx.x;   // 8-float groups
    const float4 v0 = in[2 * g];
    const float4 v1 = in[2 * g + 1];
    uint4 o;
    o.x = f2h2(v0.x, v0.y); o.y = f2h2(v0.z, v0.w);
    o.z = f2h2(v1.x, v1.y); o.w = f2h2(v1.z, v1.w);
    ((uint4*)g_xh)[g] = o;
}
__global__ __launch_bounds__(256)
void cvt_w_kernel(const float4* __restrict__ wf, const float4* __restrict__ wi,
                  const float4* __restrict__ wh) {
    const int g = blockIdx.x * 256 + threadIdx.x;          // 131072 groups per mat
    const float4* src[3] = {wf, wi, wh};
    #pragma unroll
    for (int mat = 0; mat < 3; mat++) {
        const float4 v0 = src[mat][2 * g];
        const float4 v1 = src[mat][2 * g + 1];
        uint4 o;
        o.x = f2h2(v0.x, v0.y); o.y = f2h2(v0.z, v0.w);
        o.z = f2h2(v1.x, v1.y); o.w = f2h2(v1.z, v1.w);
        ((uint4*)g_wh)[mat * 131072 + g] = o;
    }
}

// ---------------- fused GEMM (fp16 HMMA) + gates + chunk aggregates ----------------
constexpr int STAGES = 2;
constexpr int STAGE_BYTES = 40960;                   // A 16K + 3x B 8K
constexpr int S_DATA = 1024;
constexpr int SMEM_GEMM = S_DATA + STAGES * STAGE_BYTES;   // 82,944
static_assert(S_DATA + 2 * 128 * EPAD * 4 <= SMEM_GEMM, "fp32 agg arrays fit");

__global__ __launch_bounds__(256, 2)
void gemm_kernel(const __grid_constant__ CUtensorMap tA,
                 const __grid_constant__ CUtensorMap tB0,
                 const __grid_constant__ CUtensorMap tB1,
                 const __grid_constant__ CUtensorMap tB2,
                 const float* __restrict__ bf, const float* __restrict__ bi,
                 const float* __restrict__ bh)
{
    extern __shared__ char smem[];
    const uint32_t sb = smem_u32(smem);
    const int tid  = threadIdx.x;
    const int lane = tid & 31;
    const int wid  = tid >> 5;
    const int wm   = wid & 3;          // 0..3
    const int wn   = wid >> 2;         // 0..1
    const int m0   = blockIdx.x * 128;
    const int n0   = blockIdx.y * 64;
    const int gr   = lane >> 2;        // 0..7
    const int gc   = lane & 3;         // 0..3

    // ldmatrix lane geometry (SW128: addr = row*128 + (colbyte ^ ((row&7)<<4)))
    const int a_r   = wm * 32 + ((lane >> 3) & 1) * 8 + (lane & 7);
    const int a_kb  = (lane >> 4) * 16;
    const int b_nr  = wn * 32 + ((lane >> 4) & 1) * 8 + (lane & 7);
    const int b_kb  = ((lane >> 3) & 1) * 16;
    const int msk   = (lane & 7) << 4;

    // barriers: full[s] at sb+s*16, empty[s] at sb+s*16+8
    if (tid == 0) {
        for (int s = 0; s < STAGES; s++) {
            mbar_init(sb + s * 16, 1);       // full: tx-based
            mbar_init(sb + s * 16 + 8, 8);   // empty: one arrive per warp
        }
    }
    __syncthreads();
    if (tid == 0) {
        for (int s = 0; s < STAGES; s++) {
            mbar_expect_tx(sb + s * 16, STAGE_BYTES);
            const uint32_t st = sb + S_DATA + s * STAGE_BYTES;
            tma_2d(st,         &tA,  s * 64, m0, sb + s * 16);
            tma_2d(st + 16384, &tB0, s * 64, n0, sb + s * 16);
            tma_2d(st + 24576, &tB1, s * 64, n0, sb + s * 16);
            tma_2d(st + 32768, &tB2, s * 64, n0, sb + s * 16);
        }
    }

    float acc[3][2][4][4];
    #pragma unroll
    for (int m = 0; m < 3; m++)
        #pragma unroll
        for (int i = 0; i < 2; i++)
            #pragma unroll
            for (int j = 0; j < 4; j++)
                #pragma unroll
                for (int r = 0; r < 4; r++) acc[m][i][j][r] = 0.0f;

    const uint32_t stg0 = sb + S_DATA;
    const uint32_t stg1 = sb + S_DATA + STAGE_BYTES;

    for (int kt = 0; kt < 16; kt++) {
        const int s  = kt & 1;
        const int ph = (kt >> 1) & 1;
        mbar_wait(sb + s * 16, ph);
        const uint32_t uA = s ? stg1 : stg0;

        #pragma unroll
        for (int ks = 0; ks < 4; ks++) {
            const int axk = (ks * 32 + a_kb) ^ msk;
            const int bxk = (ks * 32 + b_kb) ^ msk;
            uint32_t af[2][4];
            ldsm4(af[0], uA + a_r * 128 + axk);
            ldsm4(af[1], uA + (a_r + 16) * 128 + axk);
            #pragma unroll
            for (int mat = 0; mat < 3; mat++) {
                const uint32_t uB = uA + 16384 + mat * 8192 + b_nr * 128;
                uint32_t bb[2][4];
                ldsm4(bb[0], uB + bxk);
                ldsm4(bb[1], uB + 16 * 128 + bxk);
                // early release: last smem read of this stage just completed
                if (ks == 3 && mat == 2) {
                    __syncwarp();
                    if (lane == 0) mbar_arrive(sb + s * 16 + 8);
                }
                #pragma unroll
                for (int ns = 0; ns < 4; ns++) {
                    const uint32_t b0 = bb[ns >> 1][(ns & 1) * 2];
                    const uint32_t b1 = bb[ns >> 1][(ns & 1) * 2 + 1];
                    mma16(acc[mat][0][ns], af[0], b0, b1);
                    mma16(acc[mat][1][ns], af[1], b0, b1);
                }
            }
        }

        if (tid == 0 && kt + STAGES < 16) {
            mbar_wait(sb + s * 16 + 8, ph);            // all warps released stage s
            mbar_expect_tx(sb + s * 16, STAGE_BYTES);
            const uint32_t st = s ? stg1 : stg0;
            const int kk = (kt + STAGES) * 64;
            tma_2d(st,         &tA,  kk, m0, sb + s * 16);
            tma_2d(st + 16384, &tB0, kk, n0, sb + s * 16);
            tma_2d(st + 24576, &tB1, kk, n0, sb + s * 16);
            tma_2d(st + 32768, &tB2, kk, n0, sb + s * 16);
        }
    }
    __syncthreads();   // all warps done before stage smem reuse

    // ---- epilogue: gates in regs -> direct gmem half2 + fp32 smem for aggregates ----
    float* smf = (float*)(smem + S_DATA);              // 128 x EPAD floats
    float* smv = smf + 128 * EPAD;
    __half2* gfv_base = g_fv + (long long)m0 * Hdim + n0;
    #pragma unroll
    for (int ms = 0; ms < 2; ms++) {
        #pragma unroll
        for (int ns = 0; ns < 4; ns++) {
            const int col = wn * 32 + ns * 8 + gc * 2;
            const float2 Bf = *(const float2*)(bf + n0 + col);
            const float2 Bi = *(const float2*)(bi + n0 + col);
            const float2 Bh = *(const float2*)(bh + n0 + col);
            #pragma unroll
            for (int hf = 0; hf < 2; hf++) {
                const int row = wm * 32 + ms * 16 + gr + hf * 8;
                float fv[2][2];
                #pragma unroll
                for (int e = 0; e < 2; e++) {
                    const float zf = acc[0][ms][ns][hf * 2 + e] + (e ? Bf.y : Bf.x);
                    const float zi = acc[1][ms][ns][hf * 2 + e] + (e ? Bi.y : Bi.x);
                    const float zh = acc[2][ms][ns][hf * 2 + e] + (e ? Bh.y : Bh.x);
                    const float a  = __expf(-zf);
                    const float b  = __expf(-zi);
                    const float rd = __fdividef(1.0f, 2.0f + a + b);
                    const float c  = __expf(zh);
                    const float gg = (zh >= 0.0f) ? (zh + 0.5f) : __fdividef(c, 1.0f + c);
                    fv[e][0] = (1.0f + b) * rd;          // f
                    fv[e][1] = (1.0f + a) * rd * gg;     // v
                }
                // direct gmem write: two adjacent half2 = 8B
                uint2 pk;
                pk.x = f2h2(fv[0][0], fv[0][1]);
                pk.y = f2h2(fv[1][0], fv[1][1]);
                *(uint2*)(gfv_base + (long long)row * Hdim + col) = pk;
                // fp32 copies for the chunk-aggregate pass
                *(float2*)(smf + row * EPAD + col) = make_float2(fv[0][0], fv[1][0]);
                *(float2*)(smv + row * EPAD + col) = make_float2(fv[0][1], fv[1][1]);
            }
        }
    }
    __syncthreads();

    // ---- fused chunk-scan pass 1 only (no gmem plane writes here) ----
    {
        const int ci  = tid >> 6;          // 0..3
        const int col = tid & 63;
        const int b   = m0 >> 12;
        const int cb  = (m0 & 4095) >> 5;
        float F = 1.0f, V = 0.0f;
        #pragma unroll 8
        for (int r = 0; r < 32; r++) {
            const int row = ci * 32 + r;
            const float f = smf[row * EPAD + col];
            const float v = smv[row * EPAD + col];
            V = fmaf(f, V, v);
            F *= f;
        }
        const int o = (b * NC + cb + ci) * Hdim + n0 + col;
        g_F[o] = F;
        g_V[o] = V;
    }
}

// ---------------- chunk prefix: warp-parallel affine scan ----------------
__global__ __launch_bounds__(1024)
void chunk_prefix_kernel(const float* __restrict__ h0)
{
    const int g = blockIdx.x * 32 + (threadIdx.x >> 5);
    const int l = threadIdx.x & 31;
    const int b = g >> 10;
    const int h = g & 1023;

    float Fk[4], Vk[4];
    #pragma unroll
    for (int k = 0; k < 4; k++) {
        const int o = (b * NC + 4 * l + k) * Hdim + h;
        Fk[k] = g_F[o];
        Vk[k] = g_V[o];
    }
    float Fa = Fk[0], Va = Vk[0];
    #pragma unroll
    for (int k = 1; k < 4; k++) { Va = fmaf(Fk[k], Va, Vk[k]); Fa *= Fk[k]; }
    #pragma unroll
    for (int d = 1; d < 32; d <<= 1) {
        const float Fo = __shfl_up_sync(0xFFFFFFFF, Fa, d);
        const float Vo = __shfl_up_sync(0xFFFFFFFF, Va, d);
        if (l >= d) { Va = fmaf(Fa, Vo, Va); Fa *= Fo; }
    }
    float Fe = __shfl_up_sync(0xFFFFFFFF, Fa, 1);
    float Ve = __shfl_up_sync(0xFFFFFFFF, Va, 1);
    if (l == 0) { Fe = 1.0f; Ve = 0.0f; }

    const float x = h0[b * Hdim + h];
    const float h0p = (x >= 0.0f) ? (x + 0.5f) : sigmf(x);
    float hs = fmaf(Fe, h0p, Ve);
    #pragma unroll
    for (int k = 0; k < 4; k++) {
        g_Hs[(b * NC + 4 * l + k) * Hdim + h] = hs;
        hs = fmaf(Fk[k], hs, Vk[k]);
    }
}

// ---------------- apply: within-chunk scan, write output ----------------
__global__ __launch_bounds__(1024)
void apply_kernel(float* __restrict__ out)
{
    const int h = threadIdx.x;
    const int c = blockIdx.x;
    const int b = blockIdx.y;
    float run = g_Hs[(b * NC + c) * Hdim + h];
    const __half2* fvp = g_fv + ((long long)(b * Tt + c * LCc)) * Hdim + h;
    float* op = out + ((long long)(b * Tt + c * LCc)) * Hdim + h;
    #pragma unroll 8
    for (int l = 0; l < LCc; l++) {
        const float2 fv = __half22float2(fvp[(long long)l * Hdim]);
        run = fmaf(fv.x, run, fv.y);
        op[(long long)l * Hdim] = run;
    }
}

// ---------------- host ----------------
typedef CUresult (*encode_fn_t)(CUtensorMap*, CUtensorMapDataType, cuuint32_t, void*,
                                const cuuint64_t*, const cuuint64_t*, const cuuint32_t*,
                                const cuuint32_t*, CUtensorMapInterleave, CUtensorMapSwizzle,
                                CUtensorMapL2promotion, CUtensorMapFloatOOBfill);

static void make_map(encode_fn_t enc, CUtensorMap* m, const void* ptr,
                     unsigned long long rows, unsigned box_rows)
{
    cuuint64_t dims[2]    = {1024ull, rows};
    cuuint64_t strides[1] = {2048ull};                 // fp16 row bytes
    cuuint32_t box[2]     = {64u, box_rows};           // 64 halves = 128B = SW128 atom
    cuuint32_t estr[2]    = {1u, 1u};
    enc(m, CU_TENSOR_MAP_DATA_TYPE_FLOAT16, 2, (void*)ptr, dims, strides, box, estr,
        CU_TENSOR_MAP_INTERLEAVE_NONE, CU_TENSOR_MAP_SWIZZLE_128B,
        CU_TENSOR_MAP_L2_PROMOTION_L2_128B, CU_TENSOR_MAP_FLOAT_OOB_FILL_NONE);
}

extern "C" void kernel_launch(void* const* d_in, const int* in_sizes, int n_in,
                              void* d_out, int out_size)
{
    (void)in_sizes; (void)n_in; (void)out_size;
    const float* x  = (const float*)d_in[0];
    const float* h0 = (const float*)d_in[1];
    const float* Wf = (const float*)d_in[2];
    const float* bf = (const float*)d_in[3];
    const float* Wi = (const float*)d_in[4];
    const float* bi = (const float*)d_in[5];
    const float* Wh = (const float*)d_in[6];
    const float* bh = (const float*)d_in[7];
    float* out = (float*)d_out;

    void* xh = nullptr; void* wh = nullptr;
    cudaGetSymbolAddress(&xh, g_xh);
    cudaGetSymbolAddress(&wh, g_wh);

    void* fp = nullptr;
    cudaDriverEntryPointQueryResult qres;
    cudaGetDriverEntryPointByVersion("cuTensorMapEncodeTiled", &fp, 12000,
                                     cudaEnableDefault, &qres);
    encode_fn_t enc = (encode_fn_t)fp;

    CUtensorMap tA, tB0, tB1, tB2;
    make_map(enc, &tA,  xh,                              16384ull, 128u);
    make_map(enc, &tB0, (__half*)wh,                     1024ull,  64u);
    make_map(enc, &tB1, (__half*)wh + 1024 * 1024,       1024ull,  64u);
    make_map(enc, &tB2, (__half*)wh + 2 * 1024 * 1024,   1024ull,  64u);

    cudaFuncSetAttribute(gemm_kernel,
                         cudaFuncAttributeMaxDynamicSharedMemorySize, SMEM_GEMM);

    // launch order: GEMM is 4th launch (ncu sampling lands there)
    cvt_x_kernel<<<4096, 256>>>((const float4*)x, 0);
    cvt_x_kernel<<<4096, 256>>>((const float4*)x, 1048576);
    cvt_w_kernel<<<512, 256>>>((const float4*)Wf, (const float4*)Wi, (const float4*)Wh);
    gemm_kernel<<<dim3(128, 16), 256, SMEM_GEMM>>>(tA, tB0, tB1, tB2, bf, bi, bh);
    chunk_prefix_kernel<<<128, 1024>>>(h0);
    apply_kernel<<<dim3(NC, Bb), 1024>>>(out);
}